// round 13
// baseline (speedup 1.0000x reference)
#include <cuda_runtime.h>
#include <cuda_bf16.h>
#include <math.h>
#include <stdint.h>

// Problem constants
#define Bb 32
#define Tt 128
#define Hh 1024
#define Ll 2
#define Vv 32000
#define H3 3072          // 3*H
#define MROWS (Tt*Bb)    // 4096
#define BOS 1
#define NBLK 128         // persistent recurrence blocks (all resident)

// Logits HMMA tiling (bf16): 128x256 block tile, 8 warps of 64x64
#define MT 128
#define NT 256
#define KC 64
#define NKC (Hh / KC)
#define ATILEB (MT * 128)      // 16 KB
#define BTILEB (NT * 128)      // 32 KB
#define LSMEM (2 * (ATILEB + BTILEB))   // 96 KB

// gi GEMM tiling (tf32)
#define GKC 32
#define GNKC (Hh / GKC)
#define GTILEB (128 * 128)
#define GSMEM (4 * GTILEB)              // 64 KB

// GRU smem: A(h) 32x1024 fp32 = 128KB, B(whh slice tf32) 24x1024 = 96KB
#define GRUSM (32 * 4096 + 24 * 4096)   // 229376 B

// fused log_softmax smem (one row)
#define LSMSZ (Vv * 4)

// ---------------- scratch (static device globals) ---------------------------
__device__ float g_gi[MROWS * H3];
__device__ float g_h0[MROWS * Hh];
__device__ __nv_bfloat16 g_hsb[MROWS * Hh];
__device__ __nv_bfloat16 g_wob[(size_t)Vv * Hh];
__device__ float g_hbuf[2][Bb * Hh];
__device__ int   g_ids[MROWS];
__device__ unsigned g_bar;

// ---------------- PTX helpers (all arch-portable: sm_80+) --------------------
__device__ __forceinline__ uint32_t smem_u32(const void* p) {
    uint32_t a;
    asm("{ .reg .u64 t; cvta.to.shared.u64 t, %1; cvt.u32.u64 %0, t; }"
        : "=r"(a) : "l"(p));
    return a;
}
__device__ __forceinline__ void cp_async16(uint32_t s, const void* g) {
    asm volatile("cp.async.cg.shared.global [%0], [%1], 16;"
                 :: "r"(s), "l"(g) : "memory");
}
#define CP_COMMIT() asm volatile("cp.async.commit_group;" ::: "memory")
#define CP_WAIT1()  asm volatile("cp.async.wait_group 1;" ::: "memory")
#define CP_WAIT0()  asm volatile("cp.async.wait_group 0;" ::: "memory")
#define LDSM4(r, addr) \
    asm volatile("ldmatrix.sync.aligned.m8n8.x4.shared.b16 {%0,%1,%2,%3}, [%4];" \
        : "=r"((r)[0]), "=r"((r)[1]), "=r"((r)[2]), "=r"((r)[3]) : "r"(addr))
#define MMA16816(c, a, b0, b1) \
    asm volatile("mma.sync.aligned.m16n8k16.row.col.f32.bf16.bf16.f32 " \
        "{%0,%1,%2,%3}, {%4,%5,%6,%7}, {%8,%9}, {%0,%1,%2,%3};" \
        : "+f"((c)[0]), "+f"((c)[1]), "+f"((c)[2]), "+f"((c)[3]) \
        : "r"((a)[0]), "r"((a)[1]), "r"((a)[2]), "r"((a)[3]), "r"(b0), "r"(b1))
#define MMA1688TF(c, a, b0, b1) \
    asm volatile("mma.sync.aligned.m16n8k8.row.col.f32.tf32.tf32.f32 " \
        "{%0,%1,%2,%3}, {%4,%5,%6,%7}, {%8,%9}, {%0,%1,%2,%3};" \
        : "+f"((c)[0]), "+f"((c)[1]), "+f"((c)[2]), "+f"((c)[3]) \
        : "r"((a)[0]), "r"((a)[1]), "r"((a)[2]), "r"((a)[3]), "r"(b0), "r"(b1))

__device__ __forceinline__ uint32_t lds_tf32(uint32_t addr) {
    float v; uint32_t o;
    asm("ld.shared.f32 %0, [%1];" : "=f"(v) : "r"(addr));
    asm("cvt.rna.tf32.f32 %0, %1;" : "=r"(o) : "f"(v));
    return o;
}
__device__ __forceinline__ uint32_t lds_u32(uint32_t addr) {
    uint32_t v;
    asm("ld.shared.b32 %0, [%1];" : "=r"(v) : "r"(addr));
    return v;
}
__device__ __forceinline__ uint32_t f2tf(float v) {
    uint32_t o;
    asm("cvt.rna.tf32.f32 %0, %1;" : "=r"(o) : "f"(v));
    return o;
}
// swizzle for 32-float (128B) rows
__device__ __forceinline__ uint32_t swz32(int r, int c) {
    return r * 128 + (((c >> 2) ^ (r & 7)) << 4) + ((c & 3) << 2);
}
// swizzle for 1024-float (4KB) rows
__device__ __forceinline__ uint32_t swzH(int r, int c) {
    return r * 4096 + ((((c >> 2) ^ (r & 7)) & 0xFFFF) << 4) + ((c & 3) << 2);
}

// FFMA-only e^x
__device__ __forceinline__ float fast_exp(float x) {
    float t = fmaxf(x * 1.4426950408889634f, -126.0f);
    float n = floorf(t);
    float f = t - n;
    float p = 0.0001540353f;
    p = p * f + 0.0013333558f;
    p = p * f + 0.0096181291f;
    p = p * f + 0.0555041087f;
    p = p * f + 0.2402265070f;
    p = p * f + 0.6931471806f;
    p = p * f + 1.0f;
    return __int_as_float(((int)n + 127) << 23) * p;
}

// ---------------- tiny helpers ----------------------------------------------
__global__ void copy_kernel(const float* __restrict__ src, float* __restrict__ dst, int n) {
    int i = blockIdx.x * blockDim.x + threadIdx.x;
    if (i < n) dst[i] = src[i];
}
__global__ void zero_bar_kernel() { g_bar = 0u; }
__global__ void wconv_kernel(const float* __restrict__ w) {
    size_t n = (size_t)Vv * Hh;
    size_t stride = (size_t)gridDim.x * blockDim.x;
    for (size_t i = blockIdx.x * (size_t)blockDim.x + threadIdx.x; i < n; i += stride)
        g_wob[i] = __float2bfloat16(w[i]);
}
__global__ void ids_kernel(const int* __restrict__ target) {
    int i = blockIdx.x * blockDim.x + threadIdx.x;
    if (i >= MROWS) return;
    int t = i / Bb, b = i % Bb;
    g_ids[i] = (t == 0) ? BOS : target[b * Tt + (t - 1)];
}

// ---------------- persistent GRU layer: tf32 HMMA recurrence (proven R12) ----
__global__ void __launch_bounds__(256) gru_layer_kernel(
    const float* __restrict__ gi,     // [T][B][3H]
    const float* __restrict__ whh,    // [3H][H]
    const float* __restrict__ bhh,    // [3H]
    float* __restrict__ hist,         // fp32 history (or null)
    __nv_bfloat16* __restrict__ histb,// bf16 history (or null)
    float* __restrict__ hfin,         // final h destination [B][H]
    int tS, int bS)
{
    extern __shared__ float smf[];
    float* part = smf;                 // [8][792] aliased into A region
    float* ghS  = smf + 6400;          // [24*33]  aliased into A region
    const uint32_t aBase = smem_u32(smf);
    const uint32_t bBase = aBase + 32 * 4096;

    const int tid  = threadIdx.x;
    const int lane = tid & 31;
    const int w    = tid >> 5;
    const int j0   = blockIdx.x * 8;

    const int gb = tid >> 3;          // gate-math batch 0..31
    const int gj = tid & 7;           // gate-math col 0..7
    const int j  = j0 + gj;
    const float bhr = bhh[j];
    const float bhz = bhh[Hh + j];
    const float bhn = bhh[2 * Hh + j];

    // ---- stage whh slice (24 rows) into smem, pre-converted to tf32 --------
    for (int idx = tid; idx < 24 * 256; idx += 256) {
        int n = idx >> 8, c = idx & 255;
        int grow = (n >> 3) * Hh + j0 + (n & 7);
        float4 v = *(const float4*)(whh + (size_t)grow * Hh + c * 4);
        uint4 o = make_uint4(f2tf(v.x), f2tf(v.y), f2tf(v.z), f2tf(v.w));
        *(uint4*)((char*)smf + (bBase - aBase) + n * 4096 + (((c ^ (n & 7)) & 0xFFFF) << 4)) = o;
    }
    __syncthreads();

    for (int t = 0; t < Tt; t++) {
        const float* __restrict__ hcur = g_hbuf[t & 1];
        float* __restrict__ hnxt = g_hbuf[(t + 1) & 1];

        // ---- prefetch gi[t] + hprev (consumed post-MMA; latency hidden) ----
        const float* git = gi + ((size_t)t * Bb + gb) * H3;
        float gir = git[j];
        float giz = git[Hh + j];
        float gin = git[2 * Hh + j];
        float hp  = hcur[(size_t)gb * Hh + j];

        // ---- per-warp stage of own K-slice (cols w*128..w*128+127) ----------
        {
            const int c = w * 32 + lane;      // col-quad 0..255
            #pragma unroll 8
            for (int row = 0; row < 32; row++) {
                cp_async16(aBase + row * 4096 + (((c ^ (row & 7)) & 0xFF) << 4),
                           hcur + (size_t)row * Hh + c * 4);
            }
        }
        CP_COMMIT();
        CP_WAIT0();
        __syncwarp();

        // ---- tf32 MMA: warp w covers k in [w*128, w*128+128) ---------------
        float acc[2][3][4];
        #pragma unroll
        for (int m = 0; m < 2; m++)
            #pragma unroll
            for (int nf = 0; nf < 3; nf++)
                #pragma unroll
                for (int q = 0; q < 4; q++) acc[m][nf][q] = 0.f;

        const int k0w = w * 128;
        #pragma unroll
        for (int k8 = 0; k8 < 16; k8++) {
            const int k0 = k0w + k8 * 8;
            const int cA = k0 + (lane & 3);
            uint32_t a[2][4], b[3][2];
            #pragma unroll
            for (int m = 0; m < 2; m++) {
                int r = m * 16 + (lane >> 2);
                a[m][0] = lds_tf32(aBase + swzH(r, cA));
                a[m][1] = lds_tf32(aBase + swzH(r + 8, cA));
                a[m][2] = lds_tf32(aBase + swzH(r, cA + 4));
                a[m][3] = lds_tf32(aBase + swzH(r + 8, cA + 4));
            }
            #pragma unroll
            for (int nf = 0; nf < 3; nf++) {
                int rn = nf * 8 + (lane >> 2);
                b[nf][0] = lds_u32(bBase + swzH(rn, cA));
                b[nf][1] = lds_u32(bBase + swzH(rn, cA + 4));
            }
            #pragma unroll
            for (int m = 0; m < 2; m++)
                #pragma unroll
                for (int nf = 0; nf < 3; nf++)
                    MMA1688TF(acc[m][nf], a[m], b[nf][0], b[nf][1]);
        }
        __syncthreads();   // all MMA reads of A done before aliased writes

        // ---- write partials: part[w][n*33 + m] ------------------------------
        #pragma unroll
        for (int m = 0; m < 2; m++) {
            #pragma unroll
            for (int nf = 0; nf < 3; nf++) {
                int rowm = m * 16 + (lane >> 2);
                int col = nf * 8 + 2 * (lane & 3);
                float* pw = part + w * 792;
                pw[col * 33 + rowm]           = acc[m][nf][0];
                pw[(col + 1) * 33 + rowm]     = acc[m][nf][1];
                pw[col * 33 + rowm + 8]       = acc[m][nf][2];
                pw[(col + 1) * 33 + rowm + 8] = acc[m][nf][3];
            }
        }
        __syncthreads();

        // ---- 8-way reduce -> ghS[n*33 + m] ----------------------------------
        #pragma unroll
        for (int rep = 0; rep < 3; rep++) {
            int p = rep * 256 + tid;          // p = n*32 + m
            int n = p >> 5, m = p & 31;
            float s = 0.f;
            #pragma unroll
            for (int ww = 0; ww < 8; ww++) s += part[ww * 792 + n * 33 + m];
            ghS[n * 33 + m] = s;
        }
        __syncthreads();

        // ---- gate math for owned (gb, j) ------------------------------------
        {
            float ghr = ghS[gj * 33 + gb] + bhr;
            float ghz = ghS[(8 + gj) * 33 + gb] + bhz;
            float ghn = ghS[(16 + gj) * 33 + gb] + bhn;
            float r_ = 1.f / (1.f + expf(-(gir + ghr)));
            float z_ = 1.f / (1.f + expf(-(giz + ghz)));
            float n_ = tanhf(gin + r_ * ghn);
            float hn = (1.f - z_) * n_ + z_ * hp;
            size_t oidx = (size_t)t * tS + (size_t)gb * bS + j;
            if (histb) histb[oidx] = __float2bfloat16(hn);
            else       hist[oidx] = hn;
            hnxt[(size_t)gb * Hh + j] = hn;
            if (t == Tt - 1) hfin[(size_t)gb * Hh + j] = hn;
        }

        // ---- grid barrier ----------------------------------------------------
        __threadfence();
        __syncthreads();
        if (tid == 0) {
            atomicAdd(&g_bar, 1u);
            unsigned tgt = (unsigned)(NBLK * (t + 1));
            volatile unsigned* vb = &g_bar;
            while (*vb < tgt) { __nanosleep(32); }
        }
        __syncthreads();
        __threadfence();
    }
}

// ---------------- tf32 gi GEMM (proven R10) ----------------------------------
#define GPREF(ch, p) do {                                                       \
    int _k0 = (ch) * GKC;                                                       \
    uint32_t _ab = sb + (p) * GTILEB;                                           \
    uint32_t _bb = sb + 2 * GTILEB + (p) * GTILEB;                              \
    _Pragma("unroll")                                                           \
    for (int _it = 0; _it < 4; _it++) {                                         \
        int _idx = _it * 256 + tid, _row = _idx >> 3, _c = _idx & 7;            \
        const float* _as = GATHER                                               \
            ? emb + (size_t)g_ids[m0 + _row] * Hh + _k0 + _c * 4                \
            : A + (size_t)(m0 + _row) * Hh + _k0 + _c * 4;                      \
        cp_async16(_ab + _row * 128 + ((_c ^ (_row & 7)) * 16), _as);           \
        cp_async16(_bb + _row * 128 + ((_c ^ (_row & 7)) * 16),                 \
                   W + (size_t)(n0 + _row) * Hh + _k0 + _c * 4);                \
    }                                                                           \
    CP_COMMIT();                                                                \
} while (0)

template<int GATHER>
__global__ void __launch_bounds__(256) gi_mma_kernel(
    const float* __restrict__ A, const float* __restrict__ W,
    const float* __restrict__ bias, float* __restrict__ C,
    const float* __restrict__ emb)
{
    extern __shared__ char smem[];
    const int tid  = threadIdx.x;
    const int lane = tid & 31;
    const int warp = tid >> 5;
    const int m0 = blockIdx.y * 128;
    const int n0 = blockIdx.x * 128;
    const int wm = (warp & 1) * 64;
    const int wn = (warp >> 1) * 32;
    uint32_t sb = smem_u32(smem);

    float acc[4][4][4];
    #pragma unroll
    for (int i = 0; i < 4; i++)
        #pragma unroll
        for (int jj = 0; jj < 4; jj++)
            #pragma unroll
            for (int k = 0; k < 4; k++) acc[i][jj][k] = 0.f;

    GPREF(0, 0);
    for (int ch = 0; ch < GNKC; ch++) {
        const int p = ch & 1;
        if (ch + 1 < GNKC) { GPREF(ch + 1, (ch + 1) & 1); CP_WAIT1(); }
        else               { CP_WAIT0(); }
        __syncthreads();

        const uint32_t ab = sb + p * GTILEB;
        const uint32_t bb = sb + 2 * GTILEB + p * GTILEB;
        #pragma unroll
        for (int k8 = 0; k8 < 4; k8++) {
            uint32_t a[4][4], b[4][2];
            #pragma unroll
            for (int mf = 0; mf < 4; mf++) {
                int r = wm + mf * 16 + (lane >> 2);
                int c = k8 * 8 + (lane & 3);
                a[mf][0] = lds_tf32(ab + swz32(r, c));
                a[mf][1] = lds_tf32(ab + swz32(r + 8, c));
                a[mf][2] = lds_tf32(ab + swz32(r, c + 4));
                a[mf][3] = lds_tf32(ab + swz32(r + 8, c + 4));
            }
            #pragma unroll
            for (int nf = 0; nf < 4; nf++) {
                int rn = wn + nf * 8 + (lane >> 2);
                int ck = k8 * 8 + (lane & 3);
                b[nf][0] = lds_tf32(bb + swz32(rn, ck));
                b[nf][1] = lds_tf32(bb + swz32(rn, ck + 4));
            }
            #pragma unroll
            for (int mf = 0; mf < 4; mf++)
                #pragma unroll
                for (int nf = 0; nf < 4; nf++)
                    MMA1688TF(acc[mf][nf], a[mf], b[nf][0], b[nf][1]);
        }
        __syncthreads();
    }

    #pragma unroll
    for (int mf = 0; mf < 4; mf++) {
        #pragma unroll
        for (int nf = 0; nf < 4; nf++) {
            int r  = m0 + wm + mf * 16 + (lane >> 2);
            int cg = n0 + wn + nf * 8 + (lane & 3) * 2;
            float b0 = bias[cg], b1 = bias[cg + 1];
            float2 v0 = make_float2(acc[mf][nf][0] + b0, acc[mf][nf][1] + b1);
            float2 v1 = make_float2(acc[mf][nf][2] + b0, acc[mf][nf][3] + b1);
            *(float2*)(C + (size_t)r * H3 + cg) = v0;
            *(float2*)(C + (size_t)(r + 8) * H3 + cg) = v1;
        }
    }
}

// ---------------- bf16 HMMA logits GEMM: 128x256 tile, warp 64x64 ------------
#define PREF(ch, p) do {                                                        \
    int _k0 = (ch) * KC;                                                        \
    uint32_t _ab = sb + (p) * ATILEB;                                           \
    uint32_t _bb = sb + 2 * ATILEB + (p) * BTILEB;                              \
    _Pragma("unroll")                                                           \
    for (int _it = 0; _it < 4; _it++) {                                         \
        int _idx = _it * 256 + tid, _row = _idx >> 3, _c = _idx & 7;            \
        cp_async16(_ab + _row * 128 + ((_c ^ (_row & 7)) * 16),                 \
                   hsb + (size_t)(m0 + _row) * Hh + _k0 + _c * 8);              \
    }                                                                           \
    _Pragma("unroll")                                                           \
    for (int _it = 0; _it < 8; _it++) {                                         \
        int _idx = _it * 256 + tid, _row = _idx >> 3, _c = _idx & 7;            \
        cp_async16(_bb + _row * 128 + ((_c ^ (_row & 7)) * 16),                 \
                   wob + (size_t)(n0 + _row) * Hh + _k0 + _c * 8);              \
    }                                                                           \
    CP_COMMIT();                                                                \
} while (0)

__global__ void __launch_bounds__(256) logits_mma_kernel(
    const __nv_bfloat16* __restrict__ hsb,
    const __nv_bfloat16* __restrict__ wob,
    const float* __restrict__ bias,
    float* __restrict__ out)
{
    extern __shared__ char smem[];
    const int tid  = threadIdx.x;
    const int lane = tid & 31;
    const int warp = tid >> 5;
    const int m0 = blockIdx.y * MT;
    const int n0 = blockIdx.x * NT;
    const int wm = (warp & 1) * 64;        // 2-way M split
    const int wn = (warp >> 1) * 64;       // 4-way N split (64 cols per warp)
    uint32_t sb = smem_u32(smem);

    float acc[4][8][4];
    #pragma unroll
    for (int i = 0; i < 4; i++)
        #pragma unroll
        for (int jj = 0; jj < 8; jj++)
            #pragma unroll
            for (int k = 0; k < 4; k++) acc[i][jj][k] = 0.f;

    PREF(0, 0);
    for (int ch = 0; ch < NKC; ch++) {
        const int p = ch & 1;
        if (ch + 1 < NKC) { PREF(ch + 1, (ch + 1) & 1); CP_WAIT1(); }
        else              { CP_WAIT0(); }
        __syncthreads();

        const uint32_t ab = sb + p * ATILEB;
        const uint32_t bb = sb + 2 * ATILEB + p * BTILEB;
        #pragma unroll
        for (int k16 = 0; k16 < 4; k16++) {
            uint32_t a[4][4], b[4][4];
            #pragma unroll
            for (int mf = 0; mf < 4; mf++) {
                int row = wm + mf * 16 + (lane & 7) + ((lane >> 3) & 1) * 8;
                int c = k16 * 2 + (lane >> 4);
                LDSM4(a[mf], ab + row * 128 + ((c ^ (row & 7)) * 16));
            }
            #pragma unroll
            for (int nf2 = 0; nf2 < 4; nf2++) {
                int row = wn + nf2 * 16 + (lane & 7) + ((lane >> 4) & 1) * 8;
                int c = k16 * 2 + ((lane >> 3) & 1);
                LDSM4(b[nf2], bb + row * 128 + ((c ^ (row & 7)) * 16));
            }
            #pragma unroll
            for (int mf = 0; mf < 4; mf++)
                #pragma unroll
                for (int nf = 0; nf < 8; nf++)
                    MMA16816(acc[mf][nf], a[mf],
                             b[nf >> 1][(nf & 1) * 2], b[nf >> 1][(nf & 1) * 2 + 1]);
        }
        __syncthreads();
    }

    #pragma unroll
    for (int mf = 0; mf < 4; mf++) {
        #pragma unroll
        for (int nf = 0; nf < 8; nf++) {
            int r  = m0 + wm + mf * 16 + (lane >> 2);
            int cg = n0 + wn + nf * 8 + (lane & 3) * 2;
            float b0 = bias[cg], b1 = bias[cg + 1];
            float2 v0 = make_float2(acc[mf][nf][0] + b0, acc[mf][nf][1] + b1);
            float2 v1 = make_float2(acc[mf][nf][2] + b0, acc[mf][nf][3] + b1);
            *(float2*)(out + (size_t)r * Vv + cg) = v0;
            *(float2*)(out + (size_t)(r + 8) * Vv + cg) = v1;
        }
    }
}

// ---------------- fused log_softmax (512 threads; proven R12) ----------------
__global__ void lsm_kernel(float* __restrict__ out) {
    extern __shared__ float rowbuf[];
    __shared__ float warpred[16];
    __shared__ float s_bcast;
    const int tid = threadIdx.x;
    const int lane = tid & 31, wid = tid >> 5;
    float* p = out + (size_t)blockIdx.x * Vv;

    float mx = -1e30f;
    for (int i = tid; i < Vv / 4; i += 512) {
        float4 v = *(const float4*)(p + i * 4);
        *(float4*)(rowbuf + i * 4) = v;
        mx = fmaxf(mx, fmaxf(fmaxf(v.x, v.y), fmaxf(v.z, v.w)));
    }
    #pragma unroll
    for (int s = 16; s > 0; s >>= 1)
        mx = fmaxf(mx, __shfl_xor_sync(0xffffffffu, mx, s));
    if (lane == 0) warpred[wid] = mx;
    __syncthreads();
    mx = warpred[lane & 15];
    #pragma unroll
    for (int s = 8; s > 0; s >>= 1)
        mx = fmaxf(mx, __shfl_xor_sync(0xffffffffu, mx, s));
    mx = __shfl_sync(0xffffffffu, mx, 0);

    float sum = 0.f;
    for (int i = tid; i < Vv; i += 512) sum += fast_exp(rowbuf[i] - mx);
    #pragma unroll
    for (int s = 16; s > 0; s >>= 1)
        sum += __shfl_xor_sync(0xffffffffu, sum, s);
    __syncthreads();
    if (lane == 0) warpred[wid] = sum;
    __syncthreads();
    if (tid == 0) {
        float tot = 0.f;
        #pragma unroll
        for (int w = 0; w < 16; w++) tot += warpred[w];
        s_bcast = mx + logf(tot);
    }
    __syncthreads();
    float lse = s_bcast;

    for (int i = tid; i < Vv / 4; i += 512) {
        float4 v = *(const float4*)(rowbuf + i * 4);
        v.x -= lse; v.y -= lse; v.z -= lse; v.w -= lse;
        *(float4*)(p + i * 4) = v;
    }
}

// ---------------- host driver ------------------------------------------------
extern "C" void kernel_launch(void* const* d_in, const int* in_sizes, int n_in,
                              void* d_out, int out_size) {
    const float* enc_h  = (const float*)d_in[1];
    const int*   target = (const int*)  d_in[2];
    const float* emb    = (const float*)d_in[3];
    const float* w_ih   = (const float*)d_in[4];
    const float* w_hh   = (const float*)d_in[5];
    const float* b_ih   = (const float*)d_in[6];
    const float* b_hh   = (const float*)d_in[7];
    const float* w_out  = (const float*)d_in[8];
    const float* b_out  = (const float*)d_in[9];
    float* out = (float*)d_out;

    float *p_gi, *p_h0, *p_hbuf;
    __nv_bfloat16 *p_hsb, *p_wob;
    cudaGetSymbolAddress((void**)&p_gi,   g_gi);
    cudaGetSymbolAddress((void**)&p_h0,   g_h0);
    cudaGetSymbolAddress((void**)&p_hsb,  g_hsb);
    cudaGetSymbolAddress((void**)&p_wob,  g_wob);
    cudaGetSymbolAddress((void**)&p_hbuf, g_hbuf);

    float* hfinal = out + (size_t)MROWS * Vv;

    cudaFuncSetAttribute(logits_mma_kernel,
                         cudaFuncAttributeMaxDynamicSharedMemorySize, LSMEM);
    cudaFuncSetAttribute(gi_mma_kernel<0>,
                         cudaFuncAttributeMaxDynamicSharedMemorySize, GSMEM);
    cudaFuncSetAttribute(gi_mma_kernel<1>,
                         cudaFuncAttributeMaxDynamicSharedMemorySize, GSMEM);
    cudaFuncSetAttribute(gru_layer_kernel,
                         cudaFuncAttributeMaxDynamicSharedMemorySize, GRUSM);
    cudaFuncSetAttribute(lsm_kernel,
                         cudaFuncAttributeMaxDynamicSharedMemorySize, LSMSZ);

    // ---- layer 0 -----------------------------------------------------------
    copy_kernel<<<(Bb * Hh + 255) / 256, 256, 0, 0>>>(enc_h, p_hbuf, Bb * Hh);
    zero_bar_kernel<<<1, 1, 0, 0>>>();
    ids_kernel<<<(MROWS + 255) / 256, 256, 0, 0>>>(target);
    gi_mma_kernel<1><<<dim3(H3 / 128, MROWS / 128), 256, GSMEM, 0>>>(
        nullptr, w_ih, b_ih, p_gi, emb);
    gru_layer_kernel<<<NBLK, 256, GRUSM, 0>>>(
        p_gi, w_hh, b_hh, p_h0, nullptr, hfinal, Bb * Hh, Hh);

    // ---- w_out conversion (only needed before logits) ----------------------
    wconv_kernel<<<4096, 256, 0, 0>>>(w_out);

    // ---- layer 1 -----------------------------------------------------------
    gi_mma_kernel<0><<<dim3(H3 / 128, MROWS / 128), 256, GSMEM, 0>>>(
        p_h0, w_ih + (size_t)H3 * Hh, b_ih + H3, p_gi, nullptr);
    copy_kernel<<<(Bb * Hh + 255) / 256, 256, 0, 0>>>(
        enc_h + Bb * Hh, p_hbuf, Bb * Hh);
    zero_bar_kernel<<<1, 1, 0, 0>>>();
    gru_layer_kernel<<<NBLK, 256, GRUSM, 0>>>(
        p_gi, w_hh + (size_t)H3 * Hh, b_hh + H3, nullptr, p_hsb,
        hfinal + Bb * Hh, Hh, Tt * Hh);

    // ---- logits (bf16 HMMA, 128x256) ---------------------------------------
    logits_mma_kernel<<<dim3(Vv / NT, MROWS / MT), 256, LSMEM, 0>>>(
        p_hsb, p_wob, b_out, out);

    // ---- fused log_softmax -------------------------------------------------
    lsm_kernel<<<MROWS, 512, LSMSZ, 0>>>(out);
}

// round 14
// speedup vs baseline: 1.0562x; 1.0562x over previous
#include <cuda_runtime.h>
#include <cuda_bf16.h>
#include <math.h>
#include <stdint.h>

// Problem constants
#define Bb 32
#define Tt 128
#define Hh 1024
#define Ll 2
#define Vv 32000
#define H3 3072          // 3*H
#define MROWS (Tt*Bb)    // 4096
#define BOS 1
#define NBLK 128         // persistent recurrence blocks (all resident)

// Logits HMMA tiling (bf16): 128x128 block tile, 8 warps of 64x32 (R12 proven)
#define MT 128
#define NT 128
#define KC 64
#define NKC (Hh / KC)
#define ATILEB (MT * 128)      // 16 KB
#define BTILEB (NT * 128)      // 16 KB
#define LSMEM (2 * (ATILEB + BTILEB))   // 64 KB

// gi GEMM tiling (tf32)
#define GKC 32
#define GNKC (Hh / GKC)
#define GTILEB (128 * 128)
#define GSMEM (4 * GTILEB)              // 64 KB

// GRU smem: A(h) 32x1024 fp32 = 128KB, B(whh slice tf32) 24x1024 = 96KB
#define GRUSM (32 * 4096 + 24 * 4096)   // 229376 B

// fused log_softmax smem (one row)
#define LSMSZ (Vv * 4)

// ---------------- scratch (static device globals) ---------------------------
__device__ float g_gi[MROWS * H3];
__device__ float g_h0[MROWS * Hh];
__device__ __nv_bfloat16 g_hsb[MROWS * Hh];
__device__ __nv_bfloat16 g_wob[(size_t)Vv * Hh];
__device__ float g_hbuf[2][Bb * Hh];
__device__ int   g_ids[MROWS];
__device__ unsigned g_bar;

// ---------------- PTX helpers (all arch-portable: sm_80+) --------------------
__device__ __forceinline__ uint32_t smem_u32(const void* p) {
    uint32_t a;
    asm("{ .reg .u64 t; cvta.to.shared.u64 t, %1; cvt.u32.u64 %0, t; }"
        : "=r"(a) : "l"(p));
    return a;
}
__device__ __forceinline__ void cp_async16(uint32_t s, const void* g) {
    asm volatile("cp.async.cg.shared.global [%0], [%1], 16;"
                 :: "r"(s), "l"(g) : "memory");
}
#define CP_COMMIT() asm volatile("cp.async.commit_group;" ::: "memory")
#define CP_WAIT1()  asm volatile("cp.async.wait_group 1;" ::: "memory")
#define CP_WAIT0()  asm volatile("cp.async.wait_group 0;" ::: "memory")
#define LDSM4(r, addr) \
    asm volatile("ldmatrix.sync.aligned.m8n8.x4.shared.b16 {%0,%1,%2,%3}, [%4];" \
        : "=r"((r)[0]), "=r"((r)[1]), "=r"((r)[2]), "=r"((r)[3]) : "r"(addr))
#define MMA16816(c, a, b0, b1) \
    asm volatile("mma.sync.aligned.m16n8k16.row.col.f32.bf16.bf16.f32 " \
        "{%0,%1,%2,%3}, {%4,%5,%6,%7}, {%8,%9}, {%0,%1,%2,%3};" \
        : "+f"((c)[0]), "+f"((c)[1]), "+f"((c)[2]), "+f"((c)[3]) \
        : "r"((a)[0]), "r"((a)[1]), "r"((a)[2]), "r"((a)[3]), "r"(b0), "r"(b1))
#define MMA1688TF(c, a, b0, b1) \
    asm volatile("mma.sync.aligned.m16n8k8.row.col.f32.tf32.tf32.f32 " \
        "{%0,%1,%2,%3}, {%4,%5,%6,%7}, {%8,%9}, {%0,%1,%2,%3};" \
        : "+f"((c)[0]), "+f"((c)[1]), "+f"((c)[2]), "+f"((c)[3]) \
        : "r"((a)[0]), "r"((a)[1]), "r"((a)[2]), "r"((a)[3]), "r"(b0), "r"(b1))

__device__ __forceinline__ uint32_t lds_tf32(uint32_t addr) {
    float v; uint32_t o;
    asm("ld.shared.f32 %0, [%1];" : "=f"(v) : "r"(addr));
    asm("cvt.rna.tf32.f32 %0, %1;" : "=r"(o) : "f"(v));
    return o;
}
__device__ __forceinline__ uint32_t lds_u32(uint32_t addr) {
    uint32_t v;
    asm("ld.shared.b32 %0, [%1];" : "=r"(v) : "r"(addr));
    return v;
}
__device__ __forceinline__ uint32_t f2tf(float v) {
    uint32_t o;
    asm("cvt.rna.tf32.f32 %0, %1;" : "=r"(o) : "f"(v));
    return o;
}
// swizzle for 32-float (128B) rows
__device__ __forceinline__ uint32_t swz32(int r, int c) {
    return r * 128 + (((c >> 2) ^ (r & 7)) << 4) + ((c & 3) << 2);
}
// swizzle for 1024-float (4KB) rows
__device__ __forceinline__ uint32_t swzH(int r, int c) {
    return r * 4096 + ((((c >> 2) ^ (r & 7)) & 0xFFFF) << 4) + ((c & 3) << 2);
}

// FFMA-only e^x
__device__ __forceinline__ float fast_exp(float x) {
    float t = fmaxf(x * 1.4426950408889634f, -126.0f);
    float n = floorf(t);
    float f = t - n;
    float p = 0.0001540353f;
    p = p * f + 0.0013333558f;
    p = p * f + 0.0096181291f;
    p = p * f + 0.0555041087f;
    p = p * f + 0.2402265070f;
    p = p * f + 0.6931471806f;
    p = p * f + 1.0f;
    return __int_as_float(((int)n + 127) << 23) * p;
}

// ---------------- tiny helpers ----------------------------------------------
__global__ void wconv_kernel(const float* __restrict__ w) {
    size_t n = (size_t)Vv * Hh / 4;
    size_t stride = (size_t)gridDim.x * blockDim.x;
    for (size_t i = blockIdx.x * (size_t)blockDim.x + threadIdx.x; i < n; i += stride) {
        float4 v = ((const float4*)w)[i];
        __nv_bfloat162 lo = __floats2bfloat162_rn(v.x, v.y);
        __nv_bfloat162 hi = __floats2bfloat162_rn(v.z, v.w);
        ((uint2*)g_wob)[i] = make_uint2(*(uint32_t*)&lo, *(uint32_t*)&hi);
    }
}
__global__ void ids_kernel(const int* __restrict__ target) {
    int i = blockIdx.x * blockDim.x + threadIdx.x;
    if (i >= MROWS) return;
    int t = i / Bb, b = i % Bb;
    g_ids[i] = (t == 0) ? BOS : target[b * Tt + (t - 1)];
}

// ---------------- persistent GRU layer: tf32 HMMA recurrence -----------------
// 128 blocks x 256 thr (1/SM, all resident). Block owns 8 h-cols = 24 whh
// rows staged once (tf32). Per step: per-warp cp.async of own 128-col K-slice
// of h, tf32 m16n8k8 MMA with software-pipelined B fragments (B is static in
// smem; slab-0 frags hoisted above the cp.async wait), 8-way cross-warp
// reduce via smem (aliased into dead A region), gate math on prefetched
// values, ping-pong h (step0 reads hinit directly), RELATIVE grid barrier
// (no counter reset needed between launches/replays).
__global__ void __launch_bounds__(256) gru_layer_kernel(
    const float* __restrict__ gi,     // [T][B][3H]
    const float* __restrict__ whh,    // [3H][H]
    const float* __restrict__ bhh,    // [3H]
    const float* __restrict__ hinit,  // [B][H] initial hidden state
    float* __restrict__ hist,         // fp32 history (or null)
    __nv_bfloat16* __restrict__ histb,// bf16 history (or null)
    float* __restrict__ hfin,         // final h destination [B][H]
    int tS, int bS)
{
    extern __shared__ float smf[];
    float* part = smf;                 // [8][792] aliased into A region
    float* ghS  = smf + 6400;          // [24*33]  aliased into A region
    const uint32_t aBase = smem_u32(smf);
    const uint32_t bBase = aBase + 32 * 4096;

    const int tid  = threadIdx.x;
    const int lane = tid & 31;
    const int w    = tid >> 5;
    const int j0   = blockIdx.x * 8;

    const int gb = tid >> 3;          // gate-math batch 0..31
    const int gj = tid & 7;           // gate-math col 0..7
    const int j  = j0 + gj;
    const float bhr = bhh[j];
    const float bhz = bhh[Hh + j];
    const float bhn = bhh[2 * Hh + j];

    // relative barrier base (g_bar is quiescent at kernel entry)
    const unsigned bar0 = *(volatile unsigned*)&g_bar;

    // ---- stage whh slice (24 rows) into smem, pre-converted to tf32 --------
    for (int idx = tid; idx < 24 * 256; idx += 256) {
        int n = idx >> 8, c = idx & 255;
        int grow = (n >> 3) * Hh + j0 + (n & 7);
        float4 v = *(const float4*)(whh + (size_t)grow * Hh + c * 4);
        uint4 o = make_uint4(f2tf(v.x), f2tf(v.y), f2tf(v.z), f2tf(v.w));
        *(uint4*)((char*)smf + (bBase - aBase) + n * 4096 + (((c ^ (n & 7)) & 0xFFFF) << 4)) = o;
    }
    __syncthreads();

    for (int t = 0; t < Tt; t++) {
        const float* __restrict__ hcur = (t == 0) ? hinit : g_hbuf[t & 1];
        float* __restrict__ hnxt = g_hbuf[(t + 1) & 1];

        // ---- prefetch gi[t] + hprev (consumed post-MMA; latency hidden) ----
        const float* git = gi + ((size_t)t * Bb + gb) * H3;
        float gir = git[j];
        float giz = git[Hh + j];
        float gin = git[2 * Hh + j];
        float hp  = hcur[(size_t)gb * Hh + j];

        // ---- per-warp stage of own K-slice (cols w*128..w*128+127) ----------
        {
            const int c = w * 32 + lane;      // col-quad 0..255
            #pragma unroll 8
            for (int row = 0; row < 32; row++) {
                cp_async16(aBase + row * 4096 + (((c ^ (row & 7)) & 0xFF) << 4),
                           hcur + (size_t)row * Hh + c * 4);
            }
        }
        CP_COMMIT();

        const int k0w = w * 128;
        const int cL = lane & 3;

        // ---- B fragments for slab 0 (static smem; independent of staging) --
        uint32_t bf[3][2];
        #pragma unroll
        for (int nf = 0; nf < 3; nf++) {
            int rn = nf * 8 + (lane >> 2);
            bf[nf][0] = lds_u32(bBase + swzH(rn, k0w + cL));
            bf[nf][1] = lds_u32(bBase + swzH(rn, k0w + cL + 4));
        }

        CP_WAIT0();
        __syncwarp();

        // ---- tf32 MMA: warp w covers k in [w*128, w*128+128) ---------------
        float acc[2][3][4];
        #pragma unroll
        for (int m = 0; m < 2; m++)
            #pragma unroll
            for (int nf = 0; nf < 3; nf++)
                #pragma unroll
                for (int q = 0; q < 4; q++) acc[m][nf][q] = 0.f;

        #pragma unroll
        for (int k8 = 0; k8 < 16; k8++) {
            const int cA = k0w + k8 * 8 + cL;
            uint32_t a[2][4];
            #pragma unroll
            for (int m = 0; m < 2; m++) {
                int r = m * 16 + (lane >> 2);
                a[m][0] = lds_tf32(aBase + swzH(r, cA));
                a[m][1] = lds_tf32(aBase + swzH(r + 8, cA));
                a[m][2] = lds_tf32(aBase + swzH(r, cA + 4));
                a[m][3] = lds_tf32(aBase + swzH(r + 8, cA + 4));
            }
            uint32_t bn[3][2];
            if (k8 < 15) {
                const int cB = k0w + (k8 + 1) * 8 + cL;
                #pragma unroll
                for (int nf = 0; nf < 3; nf++) {
                    int rn = nf * 8 + (lane >> 2);
                    bn[nf][0] = lds_u32(bBase + swzH(rn, cB));
                    bn[nf][1] = lds_u32(bBase + swzH(rn, cB + 4));
                }
            }
            #pragma unroll
            for (int m = 0; m < 2; m++)
                #pragma unroll
                for (int nf = 0; nf < 3; nf++)
                    MMA1688TF(acc[m][nf], a[m], bf[nf][0], bf[nf][1]);
            if (k8 < 15) {
                #pragma unroll
                for (int nf = 0; nf < 3; nf++) {
                    bf[nf][0] = bn[nf][0];
                    bf[nf][1] = bn[nf][1];
                }
            }
        }
        __syncthreads();   // all MMA reads of A done before aliased writes

        // ---- write partials: part[w][n*33 + m] ------------------------------
        #pragma unroll
        for (int m = 0; m < 2; m++) {
            #pragma unroll
            for (int nf = 0; nf < 3; nf++) {
                int rowm = m * 16 + (lane >> 2);
                int col = nf * 8 + 2 * (lane & 3);
                float* pw = part + w * 792;
                pw[col * 33 + rowm]           = acc[m][nf][0];
                pw[(col + 1) * 33 + rowm]     = acc[m][nf][1];
                pw[col * 33 + rowm + 8]       = acc[m][nf][2];
                pw[(col + 1) * 33 + rowm + 8] = acc[m][nf][3];
            }
        }
        __syncthreads();

        // ---- 8-way reduce -> ghS[n*33 + m] ----------------------------------
        #pragma unroll
        for (int rep = 0; rep < 3; rep++) {
            int p = rep * 256 + tid;          // p = n*32 + m
            int n = p >> 5, m = p & 31;
            float s = 0.f;
            #pragma unroll
            for (int ww = 0; ww < 8; ww++) s += part[ww * 792 + n * 33 + m];
            ghS[n * 33 + m] = s;
        }
        __syncthreads();

        // ---- gate math for owned (gb, j) ------------------------------------
        {
            float ghr = ghS[gj * 33 + gb] + bhr;
            float ghz = ghS[(8 + gj) * 33 + gb] + bhz;
            float ghn = ghS[(16 + gj) * 33 + gb] + bhn;
            float r_ = 1.f / (1.f + expf(-(gir + ghr)));
            float z_ = 1.f / (1.f + expf(-(giz + ghz)));
            float n_ = tanhf(gin + r_ * ghn);
            float hn = (1.f - z_) * n_ + z_ * hp;
            size_t oidx = (size_t)t * tS + (size_t)gb * bS + j;
            if (histb) histb[oidx] = __float2bfloat16(hn);
            else       hist[oidx] = hn;
            hnxt[(size_t)gb * Hh + j] = hn;
            if (t == Tt - 1) hfin[(size_t)gb * Hh + j] = hn;
        }

        // ---- relative grid barrier ------------------------------------------
        __threadfence();
        __syncthreads();
        if (tid == 0) {
            atomicAdd(&g_bar, 1u);
            unsigned tgt = (unsigned)(NBLK * (t + 1));
            volatile unsigned* vb = &g_bar;
            while ((*vb - bar0) < tgt) { __nanosleep(32); }
        }
        __syncthreads();
        __threadfence();
    }
}

// ---------------- tf32 gi GEMM (proven R10) ----------------------------------
#define GPREF(ch, p) do {                                                       \
    int _k0 = (ch) * GKC;                                                       \
    uint32_t _ab = sb + (p) * GTILEB;                                           \
    uint32_t _bb = sb + 2 * GTILEB + (p) * GTILEB;                              \
    _Pragma("unroll")                                                           \
    for (int _it = 0; _it < 4; _it++) {                                         \
        int _idx = _it * 256 + tid, _row = _idx >> 3, _c = _idx & 7;            \
        const float* _as = GATHER                                               \
            ? emb + (size_t)g_ids[m0 + _row] * Hh + _k0 + _c * 4                \
            : A + (size_t)(m0 + _row) * Hh + _k0 + _c * 4;                      \
        cp_async16(_ab + _row * 128 + ((_c ^ (_row & 7)) * 16), _as);           \
        cp_async16(_bb + _row * 128 + ((_c ^ (_row & 7)) * 16),                 \
                   W + (size_t)(n0 + _row) * Hh + _k0 + _c * 4);                \
    }                                                                           \
    CP_COMMIT();                                                                \
} while (0)

template<int GATHER>
__global__ void __launch_bounds__(256) gi_mma_kernel(
    const float* __restrict__ A, const float* __restrict__ W,
    const float* __restrict__ bias, float* __restrict__ C,
    const float* __restrict__ emb)
{
    extern __shared__ char smem[];
    const int tid  = threadIdx.x;
    const int lane = tid & 31;
    const int warp = tid >> 5;
    const int m0 = blockIdx.y * 128;
    const int n0 = blockIdx.x * 128;
    const int wm = (warp & 1) * 64;
    const int wn = (warp >> 1) * 32;
    uint32_t sb = smem_u32(smem);

    float acc[4][4][4];
    #pragma unroll
    for (int i = 0; i < 4; i++)
        #pragma unroll
        for (int jj = 0; jj < 4; jj++)
            #pragma unroll
            for (int k = 0; k < 4; k++) acc[i][jj][k] = 0.f;

    GPREF(0, 0);
    for (int ch = 0; ch < GNKC; ch++) {
        const int p = ch & 1;
        if (ch + 1 < GNKC) { GPREF(ch + 1, (ch + 1) & 1); CP_WAIT1(); }
        else               { CP_WAIT0(); }
        __syncthreads();

        const uint32_t ab = sb + p * GTILEB;
        const uint32_t bb = sb + 2 * GTILEB + p * GTILEB;
        #pragma unroll
        for (int k8 = 0; k8 < 4; k8++) {
            uint32_t a[4][4], b[4][2];
            #pragma unroll
            for (int mf = 0; mf < 4; mf++) {
                int r = wm + mf * 16 + (lane >> 2);
                int c = k8 * 8 + (lane & 3);
                a[mf][0] = lds_tf32(ab + swz32(r, c));
                a[mf][1] = lds_tf32(ab + swz32(r + 8, c));
                a[mf][2] = lds_tf32(ab + swz32(r, c + 4));
                a[mf][3] = lds_tf32(ab + swz32(r + 8, c + 4));
            }
            #pragma unroll
            for (int nf = 0; nf < 4; nf++) {
                int rn = wn + nf * 8 + (lane >> 2);
                int ck = k8 * 8 + (lane & 3);
                b[nf][0] = lds_tf32(bb + swz32(rn, ck));
                b[nf][1] = lds_tf32(bb + swz32(rn, ck + 4));
            }
            #pragma unroll
            for (int mf = 0; mf < 4; mf++)
                #pragma unroll
                for (int nf = 0; nf < 4; nf++)
                    MMA1688TF(acc[mf][nf], a[mf], b[nf][0], b[nf][1]);
        }
        __syncthreads();
    }

    #pragma unroll
    for (int mf = 0; mf < 4; mf++) {
        #pragma unroll
        for (int nf = 0; nf < 4; nf++) {
            int r  = m0 + wm + mf * 16 + (lane >> 2);
            int cg = n0 + wn + nf * 8 + (lane & 3) * 2;
            float b0 = bias[cg], b1 = bias[cg + 1];
            float2 v0 = make_float2(acc[mf][nf][0] + b0, acc[mf][nf][1] + b1);
            float2 v1 = make_float2(acc[mf][nf][2] + b0, acc[mf][nf][3] + b1);
            *(float2*)(C + (size_t)r * H3 + cg) = v0;
            *(float2*)(C + (size_t)(r + 8) * H3 + cg) = v1;
        }
    }
}

// ---------------- bf16 HMMA logits GEMM: 128x128 tile (R12 proven) -----------
#define PREF(ch, p) do {                                                        \
    int _k0 = (ch) * KC;                                                        \
    uint32_t _ab = sb + (p) * ATILEB;                                           \
    uint32_t _bb = sb + 2 * ATILEB + (p) * BTILEB;                              \
    _Pragma("unroll")                                                           \
    for (int _it = 0; _it < 4; _it++) {                                         \
        int _idx = _it * 256 + tid, _row = _idx >> 3, _c = _idx & 7;            \
        cp_async16(_ab + _row * 128 + ((_c ^ (_row & 7)) * 16),                 \
                   hsb + (size_t)(m0 + _row) * Hh + _k0 + _c * 8);              \
        cp_async16(_bb + _row * 128 + ((_c ^ (_row & 7)) * 16),                 \
                   wob + (size_t)(n0 + _row) * Hh + _k0 + _c * 8);              \
    }                                                                           \
    CP_COMMIT();                                                                \
} while (0)

__global__ void __launch_bounds__(256) logits_mma_kernel(
    const __nv_bfloat16* __restrict__ hsb,
    const __nv_bfloat16* __restrict__ wob,
    const float* __restrict__ bias,
    float* __restrict__ out)
{
    extern __shared__ char smem[];
    const int tid  = threadIdx.x;
    const int lane = tid & 31;
    const int warp = tid >> 5;
    const int m0 = blockIdx.y * MT;
    const int n0 = blockIdx.x * NT;
    const int wm = (warp & 1) * 64;
    const int wn = (warp >> 1) * 32;
    uint32_t sb = smem_u32(smem);

    float acc[4][4][4];
    #pragma unroll
    for (int i = 0; i < 4; i++)
        #pragma unroll
        for (int jj = 0; jj < 4; jj++)
            #pragma unroll
            for (int k = 0; k < 4; k++) acc[i][jj][k] = 0.f;

    PREF(0, 0);
    for (int ch = 0; ch < NKC; ch++) {
        const int p = ch & 1;
        if (ch + 1 < NKC) { PREF(ch + 1, (ch + 1) & 1); CP_WAIT1(); }
        else              { CP_WAIT0(); }
        __syncthreads();

        const uint32_t ab = sb + p * ATILEB;
        const uint32_t bb = sb + 2 * ATILEB + p * BTILEB;
        #pragma unroll
        for (int k16 = 0; k16 < 4; k16++) {
            uint32_t a[4][4], b[2][4];
            #pragma unroll
            for (int mf = 0; mf < 4; mf++) {
                int row = wm + mf * 16 + (lane & 7) + ((lane >> 3) & 1) * 8;
                int c = k16 * 2 + (lane >> 4);
                LDSM4(a[mf], ab + row * 128 + ((c ^ (row & 7)) * 16));
            }
            #pragma unroll
            for (int nf2 = 0; nf2 < 2; nf2++) {
                int row = wn + nf2 * 16 + (lane & 7) + ((lane >> 4) & 1) * 8;
                int c = k16 * 2 + ((lane >> 3) & 1);
                LDSM4(b[nf2], bb + row * 128 + ((c ^ (row & 7)) * 16));
            }
            #pragma unroll
            for (int mf = 0; mf < 4; mf++)
                #pragma unroll
                for (int nf = 0; nf < 4; nf++)
                    MMA16816(acc[mf][nf], a[mf],
                             b[nf >> 1][(nf & 1) * 2], b[nf >> 1][(nf & 1) * 2 + 1]);
        }
        __syncthreads();
    }

    #pragma unroll
    for (int mf = 0; mf < 4; mf++) {
        #pragma unroll
        for (int nf = 0; nf < 4; nf++) {
            int r  = m0 + wm + mf * 16 + (lane >> 2);
            int cg = n0 + wn + nf * 8 + (lane & 3) * 2;
            float b0 = bias[cg], b1 = bias[cg + 1];
            float2 v0 = make_float2(acc[mf][nf][0] + b0, acc[mf][nf][1] + b1);
            float2 v1 = make_float2(acc[mf][nf][2] + b0, acc[mf][nf][3] + b1);
            *(float2*)(out + (size_t)r * Vv + cg) = v0;
            *(float2*)(out + (size_t)(r + 8) * Vv + cg) = v1;
        }
    }
}

// ---------------- fused log_softmax (512 threads; proven R12) ----------------
__global__ void lsm_kernel(float* __restrict__ out) {
    extern __shared__ float rowbuf[];
    __shared__ float warpred[16];
    __shared__ float s_bcast;
    const int tid = threadIdx.x;
    const int lane = tid & 31, wid = tid >> 5;
    float* p = out + (size_t)blockIdx.x * Vv;

    float mx = -1e30f;
    for (int i = tid; i < Vv / 4; i += 512) {
        float4 v = *(const float4*)(p + i * 4);
        *(float4*)(rowbuf + i * 4) = v;
        mx = fmaxf(mx, fmaxf(fmaxf(v.x, v.y), fmaxf(v.z, v.w)));
    }
    #pragma unroll
    for (int s = 16; s > 0; s >>= 1)
        mx = fmaxf(mx, __shfl_xor_sync(0xffffffffu, mx, s));
    if (lane == 0) warpred[wid] = mx;
    __syncthreads();
    mx = warpred[lane & 15];
    #pragma unroll
    for (int s = 8; s > 0; s >>= 1)
        mx = fmaxf(mx, __shfl_xor_sync(0xffffffffu, mx, s));
    mx = __shfl_sync(0xffffffffu, mx, 0);

    float sum = 0.f;
    for (int i = tid; i < Vv; i += 512) sum += fast_exp(rowbuf[i] - mx);
    #pragma unroll
    for (int s = 16; s > 0; s >>= 1)
        sum += __shfl_xor_sync(0xffffffffu, sum, s);
    __syncthreads();
    if (lane == 0) warpred[wid] = sum;
    __syncthreads();
    if (tid == 0) {
        float tot = 0.f;
        #pragma unroll
        for (int w = 0; w < 16; w++) tot += warpred[w];
        s_bcast = mx + logf(tot);
    }
    __syncthreads();
    float lse = s_bcast;

    for (int i = tid; i < Vv / 4; i += 512) {
        float4 v = *(const float4*)(rowbuf + i * 4);
        v.x -= lse; v.y -= lse; v.z -= lse; v.w -= lse;
        *(float4*)(p + i * 4) = v;
    }
}

// ---------------- host driver ------------------------------------------------
extern "C" void kernel_launch(void* const* d_in, const int* in_sizes, int n_in,
                              void* d_out, int out_size) {
    const float* enc_h  = (const float*)d_in[1];
    const int*   target = (const int*)  d_in[2];
    const float* emb    = (const float*)d_in[3];
    const float* w_ih   = (const float*)d_in[4];
    const float* w_hh   = (const float*)d_in[5];
    const float* b_ih   = (const float*)d_in[6];
    const float* b_hh   = (const float*)d_in[7];
    const float* w_out  = (const float*)d_in[8];
    const float* b_out  = (const float*)d_in[9];
    float* out = (float*)d_out;

    float *p_gi, *p_h0;
    __nv_bfloat16 *p_hsb, *p_wob;
    cudaGetSymbolAddress((void**)&p_gi,   g_gi);
    cudaGetSymbolAddress((void**)&p_h0,   g_h0);
    cudaGetSymbolAddress((void**)&p_hsb,  g_hsb);
    cudaGetSymbolAddress((void**)&p_wob,  g_wob);

    float* hfinal = out + (size_t)MROWS * Vv;

    cudaFuncSetAttribute(logits_mma_kernel,
                         cudaFuncAttributeMaxDynamicSharedMemorySize, LSMEM);
    cudaFuncSetAttribute(gi_mma_kernel<0>,
                         cudaFuncAttributeMaxDynamicSharedMemorySize, GSMEM);
    cudaFuncSetAttribute(gi_mma_kernel<1>,
                         cudaFuncAttributeMaxDynamicSharedMemorySize, GSMEM);
    cudaFuncSetAttribute(gru_layer_kernel,
                         cudaFuncAttributeMaxDynamicSharedMemorySize, GRUSM);
    cudaFuncSetAttribute(lsm_kernel,
                         cudaFuncAttributeMaxDynamicSharedMemorySize, LSMSZ);

    // ---- layer 0 -----------------------------------------------------------
    ids_kernel<<<(MROWS + 255) / 256, 256, 0, 0>>>(target);
    gi_mma_kernel<1><<<dim3(H3 / 128, MROWS / 128), 256, GSMEM, 0>>>(
        nullptr, w_ih, b_ih, p_gi, emb);
    gru_layer_kernel<<<NBLK, 256, GRUSM, 0>>>(
        p_gi, w_hh, b_hh, enc_h, p_h0, nullptr, hfinal, Bb * Hh, Hh);

    // ---- w_out conversion (only needed before logits) ----------------------
    wconv_kernel<<<4096, 256, 0, 0>>>(w_out);

    // ---- layer 1 -----------------------------------------------------------
    gi_mma_kernel<0><<<dim3(H3 / 128, MROWS / 128), 256, GSMEM, 0>>>(
        p_h0, w_ih + (size_t)H3 * Hh, b_ih + H3, p_gi, nullptr);
    gru_layer_kernel<<<NBLK, 256, GRUSM, 0>>>(
        p_gi, w_hh + (size_t)H3 * Hh, b_hh + H3, enc_h + Bb * Hh,
        nullptr, p_hsb, hfinal + Bb * Hh, Hh, Tt * Hh);

    // ---- logits (bf16 HMMA, 128x128) ---------------------------------------
    logits_mma_kernel<<<dim3(Vv / NT, MROWS / MT), 256, LSMEM, 0>>>(
        p_hsb, p_wob, b_out, out);

    // ---- fused log_softmax -------------------------------------------------
    lsm_kernel<<<MROWS, 512, LSMSZ, 0>>>(out);
}

// round 15
// speedup vs baseline: 1.1111x; 1.0519x over previous
#include <cuda_runtime.h>
#include <cuda_bf16.h>
#include <math.h>
#include <stdint.h>

// Problem constants
#define Bb 32
#define Tt 128
#define Hh 1024
#define Ll 2
#define Vv 32000
#define H3 3072          // 3*H
#define MROWS (Tt*Bb)    // 4096
#define BOS 1
#define NBLK 128         // persistent recurrence blocks (all resident)

// Logits HMMA tiling (bf16): 128x128 block tile, 8 warps of 64x32 (R12 proven)
#define MT 128
#define NT 128
#define KC 64
#define NKC (Hh / KC)
#define ATILEB (MT * 128)      // 16 KB
#define BTILEB (NT * 128)      // 16 KB
#define LSMEM (2 * (ATILEB + BTILEB))   // 64 KB

// gi GEMM tiling (tf32)
#define GKC 32
#define GNKC (Hh / GKC)
#define GTILEB (128 * 128)
#define GSMEM (4 * GTILEB)              // 64 KB

// GRU smem: A(h) 32x1024 fp32 = 128KB, B(whh slice tf32) 24x1024 = 96KB
#define GRUSM (32 * 4096 + 24 * 4096)   // 229376 B

// fused log_softmax smem (one row)
#define LSMSZ (Vv * 4)

// ---------------- scratch (static device globals) ---------------------------
__device__ float g_gi[MROWS * H3];
__device__ float g_h0[MROWS * Hh];           // layer-0 outputs (tf32-rounded bits)
__device__ float g_wih_tf[Ll * H3 * Hh];     // w_ih pre-converted to tf32 bits
__device__ __nv_bfloat16 g_hsb[MROWS * Hh];
__device__ __nv_bfloat16 g_wob[(size_t)Vv * Hh];
__device__ float g_hbuf[2][Bb * Hh];
__device__ int   g_ids[MROWS];
__device__ unsigned g_bar;

// ---------------- PTX helpers (all arch-portable: sm_80+) --------------------
__device__ __forceinline__ uint32_t smem_u32(const void* p) {
    uint32_t a;
    asm("{ .reg .u64 t; cvta.to.shared.u64 t, %1; cvt.u32.u64 %0, t; }"
        : "=r"(a) : "l"(p));
    return a;
}
__device__ __forceinline__ void cp_async16(uint32_t s, const void* g) {
    asm volatile("cp.async.cg.shared.global [%0], [%1], 16;"
                 :: "r"(s), "l"(g) : "memory");
}
#define CP_COMMIT() asm volatile("cp.async.commit_group;" ::: "memory")
#define CP_WAIT1()  asm volatile("cp.async.wait_group 1;" ::: "memory")
#define CP_WAIT0()  asm volatile("cp.async.wait_group 0;" ::: "memory")
#define LDSM4(r, addr) \
    asm volatile("ldmatrix.sync.aligned.m8n8.x4.shared.b16 {%0,%1,%2,%3}, [%4];" \
        : "=r"((r)[0]), "=r"((r)[1]), "=r"((r)[2]), "=r"((r)[3]) : "r"(addr))
#define MMA16816(c, a, b0, b1) \
    asm volatile("mma.sync.aligned.m16n8k16.row.col.f32.bf16.bf16.f32 " \
        "{%0,%1,%2,%3}, {%4,%5,%6,%7}, {%8,%9}, {%0,%1,%2,%3};" \
        : "+f"((c)[0]), "+f"((c)[1]), "+f"((c)[2]), "+f"((c)[3]) \
        : "r"((a)[0]), "r"((a)[1]), "r"((a)[2]), "r"((a)[3]), "r"(b0), "r"(b1))
#define MMA1688TF(c, a, b0, b1) \
    asm volatile("mma.sync.aligned.m16n8k8.row.col.f32.tf32.tf32.f32 " \
        "{%0,%1,%2,%3}, {%4,%5,%6,%7}, {%8,%9}, {%0,%1,%2,%3};" \
        : "+f"((c)[0]), "+f"((c)[1]), "+f"((c)[2]), "+f"((c)[3]) \
        : "r"((a)[0]), "r"((a)[1]), "r"((a)[2]), "r"((a)[3]), "r"(b0), "r"(b1))

__device__ __forceinline__ uint32_t lds_tf32(uint32_t addr) {
    float v; uint32_t o;
    asm("ld.shared.f32 %0, [%1];" : "=f"(v) : "r"(addr));
    asm("cvt.rna.tf32.f32 %0, %1;" : "=r"(o) : "f"(v));
    return o;
}
__device__ __forceinline__ uint32_t lds_u32(uint32_t addr) {
    uint32_t v;
    asm("ld.shared.b32 %0, [%1];" : "=r"(v) : "r"(addr));
    return v;
}
__device__ __forceinline__ uint32_t f2tf(float v) {
    uint32_t o;
    asm("cvt.rna.tf32.f32 %0, %1;" : "=r"(o) : "f"(v));
    return o;
}
// swizzle for 32-float (128B) rows
__device__ __forceinline__ uint32_t swz32(int r, int c) {
    return r * 128 + (((c >> 2) ^ (r & 7)) << 4) + ((c & 3) << 2);
}
// swizzle for 1024-float (4KB) rows
__device__ __forceinline__ uint32_t swzH(int r, int c) {
    return r * 4096 + ((((c >> 2) ^ (r & 7)) & 0xFFFF) << 4) + ((c & 3) << 2);
}

// FFMA-only e^x
__device__ __forceinline__ float fast_exp(float x) {
    float t = fmaxf(x * 1.4426950408889634f, -126.0f);
    float n = floorf(t);
    float f = t - n;
    float p = 0.0001540353f;
    p = p * f + 0.0013333558f;
    p = p * f + 0.0096181291f;
    p = p * f + 0.0555041087f;
    p = p * f + 0.2402265070f;
    p = p * f + 0.6931471806f;
    p = p * f + 1.0f;
    return __int_as_float(((int)n + 127) << 23) * p;
}

// ---------------- tiny helpers ----------------------------------------------
__global__ void wconv_kernel(const float* __restrict__ w) {
    size_t n = (size_t)Vv * Hh / 4;
    size_t stride = (size_t)gridDim.x * blockDim.x;
    for (size_t i = blockIdx.x * (size_t)blockDim.x + threadIdx.x; i < n; i += stride) {
        float4 v = ((const float4*)w)[i];
        __nv_bfloat162 lo = __floats2bfloat162_rn(v.x, v.y);
        __nv_bfloat162 hi = __floats2bfloat162_rn(v.z, v.w);
        ((uint2*)g_wob)[i] = make_uint2(*(uint32_t*)&lo, *(uint32_t*)&hi);
    }
}
// pre-convert both layers' w_ih to tf32 bit patterns (idempotent vs in-kernel cvt)
__global__ void wihconv_kernel(const float* __restrict__ w) {
    size_t n = (size_t)Ll * H3 * Hh / 4;
    size_t stride = (size_t)gridDim.x * blockDim.x;
    for (size_t i = blockIdx.x * (size_t)blockDim.x + threadIdx.x; i < n; i += stride) {
        float4 v = ((const float4*)w)[i];
        uint4 o = make_uint4(f2tf(v.x), f2tf(v.y), f2tf(v.z), f2tf(v.w));
        ((uint4*)g_wih_tf)[i] = o;
    }
}
__global__ void ids_kernel(const int* __restrict__ target) {
    int i = blockIdx.x * blockDim.x + threadIdx.x;
    if (i >= MROWS) return;
    int t = i / Bb, b = i % Bb;
    g_ids[i] = (t == 0) ? BOS : target[b * Tt + (t - 1)];
}

// ---------------- persistent GRU layer: tf32 HMMA recurrence -----------------
// 128 blocks x 256 thr (1/SM, all resident). Block owns 8 h-cols = 24 whh
// rows staged once (tf32). Per step: per-warp cp.async of own 128-col K-slice
// of h, tf32 m16n8k8 MMA with pipelined B fragments, cross-warp reduce fused
// directly into gate math (reduce thread (m=tid>>3, col=tid&7) owns exactly
// its gate element), ping-pong h, release/acquire grid barrier (CG pattern,
// no membar.gl), relative counter (no reset kernel).
// TFH: write fp32-history tf32-rounded (consumed only by gi MMA whose cvt.rna
// is idempotent -> bit-identical results, but lets gi skip the cvt).
__global__ void __launch_bounds__(256) gru_layer_kernel(
    const float* __restrict__ gi,     // [T][B][3H]
    const float* __restrict__ whh,    // [3H][H]
    const float* __restrict__ bhh,    // [3H]
    const float* __restrict__ hinit,  // [B][H] initial hidden state
    float* __restrict__ hist,         // fp32 history (tf32-rounded; or null)
    __nv_bfloat16* __restrict__ histb,// bf16 history (or null)
    float* __restrict__ hfin,         // final h destination [B][H] (exact fp32)
    int tS, int bS)
{
    extern __shared__ float smf[];
    float* part = smf;                 // [8][792] aliased into A region
    const uint32_t aBase = smem_u32(smf);
    const uint32_t bBase = aBase + 32 * 4096;

    const int tid  = threadIdx.x;
    const int lane = tid & 31;
    const int w    = tid >> 5;
    const int j0   = blockIdx.x * 8;

    const int gb = tid >> 3;          // gate-math batch 0..31
    const int gj = tid & 7;           // gate-math col 0..7
    const int j  = j0 + gj;
    const float bhr = bhh[j];
    const float bhz = bhh[Hh + j];
    const float bhn = bhh[2 * Hh + j];

    // relative barrier base (g_bar is quiescent at kernel entry)
    const unsigned bar0 = *(volatile unsigned*)&g_bar;

    // ---- stage whh slice (24 rows) into smem, pre-converted to tf32 --------
    for (int idx = tid; idx < 24 * 256; idx += 256) {
        int n = idx >> 8, c = idx & 255;
        int grow = (n >> 3) * Hh + j0 + (n & 7);
        float4 v = *(const float4*)(whh + (size_t)grow * Hh + c * 4);
        uint4 o = make_uint4(f2tf(v.x), f2tf(v.y), f2tf(v.z), f2tf(v.w));
        *(uint4*)((char*)smf + (bBase - aBase) + n * 4096 + (((c ^ (n & 7)) & 0xFFFF) << 4)) = o;
    }
    __syncthreads();

    for (int t = 0; t < Tt; t++) {
        const float* __restrict__ hcur = (t == 0) ? hinit : g_hbuf[t & 1];
        float* __restrict__ hnxt = g_hbuf[(t + 1) & 1];

        // ---- prefetch gi[t] + hprev (consumed post-MMA; latency hidden) ----
        const float* git = gi + ((size_t)t * Bb + gb) * H3;
        float gir = git[j];
        float giz = git[Hh + j];
        float gin = git[2 * Hh + j];
        float hp  = hcur[(size_t)gb * Hh + j];

        // ---- per-warp stage of own K-slice (cols w*128..w*128+127) ----------
        {
            const int c = w * 32 + lane;      // col-quad 0..255
            #pragma unroll 8
            for (int row = 0; row < 32; row++) {
                cp_async16(aBase + row * 4096 + (((c ^ (row & 7)) & 0xFF) << 4),
                           hcur + (size_t)row * Hh + c * 4);
            }
        }
        CP_COMMIT();

        const int k0w = w * 128;
        const int cL = lane & 3;

        // ---- B fragments for slab 0 (static smem; independent of staging) --
        uint32_t bf[3][2];
        #pragma unroll
        for (int nf = 0; nf < 3; nf++) {
            int rn = nf * 8 + (lane >> 2);
            bf[nf][0] = lds_u32(bBase + swzH(rn, k0w + cL));
            bf[nf][1] = lds_u32(bBase + swzH(rn, k0w + cL + 4));
        }

        CP_WAIT0();
        __syncwarp();

        // ---- tf32 MMA: warp w covers k in [w*128, w*128+128) ---------------
        float acc[2][3][4];
        #pragma unroll
        for (int m = 0; m < 2; m++)
            #pragma unroll
            for (int nf = 0; nf < 3; nf++)
                #pragma unroll
                for (int q = 0; q < 4; q++) acc[m][nf][q] = 0.f;

        #pragma unroll
        for (int k8 = 0; k8 < 16; k8++) {
            const int cA = k0w + k8 * 8 + cL;
            uint32_t a[2][4];
            #pragma unroll
            for (int m = 0; m < 2; m++) {
                int r = m * 16 + (lane >> 2);
                a[m][0] = lds_tf32(aBase + swzH(r, cA));
                a[m][1] = lds_tf32(aBase + swzH(r + 8, cA));
                a[m][2] = lds_tf32(aBase + swzH(r, cA + 4));
                a[m][3] = lds_tf32(aBase + swzH(r + 8, cA + 4));
            }
            uint32_t bn[3][2];
            if (k8 < 15) {
                const int cB = k0w + (k8 + 1) * 8 + cL;
                #pragma unroll
                for (int nf = 0; nf < 3; nf++) {
                    int rn = nf * 8 + (lane >> 2);
                    bn[nf][0] = lds_u32(bBase + swzH(rn, cB));
                    bn[nf][1] = lds_u32(bBase + swzH(rn, cB + 4));
                }
            }
            #pragma unroll
            for (int m = 0; m < 2; m++)
                #pragma unroll
                for (int nf = 0; nf < 3; nf++)
                    MMA1688TF(acc[m][nf], a[m], bf[nf][0], bf[nf][1]);
            if (k8 < 15) {
                #pragma unroll
                for (int nf = 0; nf < 3; nf++) {
                    bf[nf][0] = bn[nf][0];
                    bf[nf][1] = bn[nf][1];
                }
            }
        }
        __syncthreads();   // all MMA reads of A done before aliased writes

        // ---- write partials: part[w][rid*33 + batch] ------------------------
        #pragma unroll
        for (int m = 0; m < 2; m++) {
            #pragma unroll
            for (int nf = 0; nf < 3; nf++) {
                int rowm = m * 16 + (lane >> 2);
                int col = nf * 8 + 2 * (lane & 3);
                float* pw = part + w * 792;
                pw[col * 33 + rowm]           = acc[m][nf][0];
                pw[(col + 1) * 33 + rowm]     = acc[m][nf][1];
                pw[col * 33 + rowm + 8]       = acc[m][nf][2];
                pw[(col + 1) * 33 + rowm + 8] = acc[m][nf][3];
            }
        }
        __syncthreads();

        // ---- fused 8-way reduce + gate math: thread owns (gb, gj) -----------
        {
            float ghr = bhr, ghz = bhz, ghn = bhn;
            #pragma unroll
            for (int ww = 0; ww < 8; ww++) {
                const float* pw = part + ww * 792;
                ghr += pw[gj * 33 + gb];
                ghz += pw[(8 + gj) * 33 + gb];
                ghn += pw[(16 + gj) * 33 + gb];
            }
            float r_ = 1.f / (1.f + expf(-(gir + ghr)));
            float z_ = 1.f / (1.f + expf(-(giz + ghz)));
            float n_ = tanhf(gin + r_ * ghn);
            float hn = (1.f - z_) * n_ + z_ * hp;
            size_t oidx = (size_t)t * tS + (size_t)gb * bS + j;
            if (histb) histb[oidx] = __float2bfloat16(hn);
            else       hist[oidx] = __uint_as_float(f2tf(hn));   // tf32 pre-round
            hnxt[(size_t)gb * Hh + j] = hn;
            if (t == Tt - 1) hfin[(size_t)gb * Hh + j] = hn;
        }

        // ---- grid barrier (release/acquire, CG pattern) ---------------------
        __syncthreads();
        if (tid == 0) {
            asm volatile("red.release.gpu.add.u32 [%0], %1;"
                         :: "l"(&g_bar), "r"(1u) : "memory");
            unsigned tgt = (unsigned)(NBLK * (t + 1));
            unsigned v;
            do {
                asm volatile("ld.acquire.gpu.u32 %0, [%1];"
                             : "=r"(v) : "l"(&g_bar) : "memory");
                if ((v - bar0) >= tgt) break;
                __nanosleep(32);
            } while (true);
        }
        __syncthreads();
    }
}

// ---------------- tf32 gi GEMM: B always pre-tf32; A pre-tf32 unless GATHER --
#define GPREF(ch, p) do {                                                       \
    int _k0 = (ch) * GKC;                                                       \
    uint32_t _ab = sb + (p) * GTILEB;                                           \
    uint32_t _bb = sb + 2 * GTILEB + (p) * GTILEB;                              \
    _Pragma("unroll")                                                           \
    for (int _it = 0; _it < 4; _it++) {                                         \
        int _idx = _it * 256 + tid, _row = _idx >> 3, _c = _idx & 7;            \
        const float* _as = GATHER                                               \
            ? emb + (size_t)g_ids[m0 + _row] * Hh + _k0 + _c * 4                \
            : A + (size_t)(m0 + _row) * Hh + _k0 + _c * 4;                      \
        cp_async16(_ab + _row * 128 + ((_c ^ (_row & 7)) * 16), _as);           \
        cp_async16(_bb + _row * 128 + ((_c ^ (_row & 7)) * 16),                 \
                   W + (size_t)(n0 + _row) * Hh + _k0 + _c * 4);                \
    }                                                                           \
    CP_COMMIT();                                                                \
} while (0)

template<int GATHER>
__global__ void __launch_bounds__(256) gi_mma_kernel(
    const float* __restrict__ A, const float* __restrict__ W,
    const float* __restrict__ bias, float* __restrict__ C,
    const float* __restrict__ emb)
{
    extern __shared__ char smem[];
    const int tid  = threadIdx.x;
    const int lane = tid & 31;
    const int warp = tid >> 5;
    const int m0 = blockIdx.y * 128;
    const int n0 = blockIdx.x * 128;
    const int wm = (warp & 1) * 64;
    const int wn = (warp >> 1) * 32;
    uint32_t sb = smem_u32(smem);

    float acc[4][4][4];
    #pragma unroll
    for (int i = 0; i < 4; i++)
        #pragma unroll
        for (int jj = 0; jj < 4; jj++)
            #pragma unroll
            for (int k = 0; k < 4; k++) acc[i][jj][k] = 0.f;

    GPREF(0, 0);
    for (int ch = 0; ch < GNKC; ch++) {
        const int p = ch & 1;
        if (ch + 1 < GNKC) { GPREF(ch + 1, (ch + 1) & 1); CP_WAIT1(); }
        else               { CP_WAIT0(); }
        __syncthreads();

        const uint32_t ab = sb + p * GTILEB;
        const uint32_t bb = sb + 2 * GTILEB + p * GTILEB;
        #pragma unroll
        for (int k8 = 0; k8 < 4; k8++) {
            uint32_t a[4][4], b[4][2];
            #pragma unroll
            for (int mf = 0; mf < 4; mf++) {
                int r = wm + mf * 16 + (lane >> 2);
                int c = k8 * 8 + (lane & 3);
                if (GATHER) {
                    a[mf][0] = lds_tf32(ab + swz32(r, c));
                    a[mf][1] = lds_tf32(ab + swz32(r + 8, c));
                    a[mf][2] = lds_tf32(ab + swz32(r, c + 4));
                    a[mf][3] = lds_tf32(ab + swz32(r + 8, c + 4));
                } else {
                    a[mf][0] = lds_u32(ab + swz32(r, c));
                    a[mf][1] = lds_u32(ab + swz32(r + 8, c));
                    a[mf][2] = lds_u32(ab + swz32(r, c + 4));
                    a[mf][3] = lds_u32(ab + swz32(r + 8, c + 4));
                }
            }
            #pragma unroll
            for (int nf = 0; nf < 4; nf++) {
                int rn = wn + nf * 8 + (lane >> 2);
                int ck = k8 * 8 + (lane & 3);
                b[nf][0] = lds_u32(bb + swz32(rn, ck));
                b[nf][1] = lds_u32(bb + swz32(rn, ck + 4));
            }
            #pragma unroll
            for (int mf = 0; mf < 4; mf++)
                #pragma unroll
                for (int nf = 0; nf < 4; nf++)
                    MMA1688TF(acc[mf][nf], a[mf], b[nf][0], b[nf][1]);
        }
        __syncthreads();
    }

    #pragma unroll
    for (int mf = 0; mf < 4; mf++) {
        #pragma unroll
        for (int nf = 0; nf < 4; nf++) {
            int r  = m0 + wm + mf * 16 + (lane >> 2);
            int cg = n0 + wn + nf * 8 + (lane & 3) * 2;
            float b0 = bias[cg], b1 = bias[cg + 1];
            float2 v0 = make_float2(acc[mf][nf][0] + b0, acc[mf][nf][1] + b1);
            float2 v1 = make_float2(acc[mf][nf][2] + b0, acc[mf][nf][3] + b1);
            *(float2*)(C + (size_t)r * H3 + cg) = v0;
            *(float2*)(C + (size_t)(r + 8) * H3 + cg) = v1;
        }
    }
}

// ---------------- bf16 HMMA logits GEMM: 128x128 tile (R12 proven) -----------
#define PREF(ch, p) do {                                                        \
    int _k0 = (ch) * KC;                                                        \
    uint32_t _ab = sb + (p) * ATILEB;                                           \
    uint32_t _bb = sb + 2 * ATILEB + (p) * BTILEB;                              \
    _Pragma("unroll")                                                           \
    for (int _it = 0; _it < 4; _it++) {                                         \
        int _idx = _it * 256 + tid, _row = _idx >> 3, _c = _idx & 7;            \
        cp_async16(_ab + _row * 128 + ((_c ^ (_row & 7)) * 16),                 \
                   hsb + (size_t)(m0 + _row) * Hh + _k0 + _c * 8);              \
        cp_async16(_bb + _row * 128 + ((_c ^ (_row & 7)) * 16),                 \
                   wob + (size_t)(n0 + _row) * Hh + _k0 + _c * 8);              \
    }                                                                           \
    CP_COMMIT();                                                                \
} while (0)

__global__ void __launch_bounds__(256) logits_mma_kernel(
    const __nv_bfloat16* __restrict__ hsb,
    const __nv_bfloat16* __restrict__ wob,
    const float* __restrict__ bias,
    float* __restrict__ out)
{
    extern __shared__ char smem[];
    const int tid  = threadIdx.x;
    const int lane = tid & 31;
    const int warp = tid >> 5;
    const int m0 = blockIdx.y * MT;
    const int n0 = blockIdx.x * NT;
    const int wm = (warp & 1) * 64;
    const int wn = (warp >> 1) * 32;
    uint32_t sb = smem_u32(smem);

    float acc[4][4][4];
    #pragma unroll
    for (int i = 0; i < 4; i++)
        #pragma unroll
        for (int jj = 0; jj < 4; jj++)
            #pragma unroll
            for (int k = 0; k < 4; k++) acc[i][jj][k] = 0.f;

    PREF(0, 0);
    for (int ch = 0; ch < NKC; ch++) {
        const int p = ch & 1;
        if (ch + 1 < NKC) { PREF(ch + 1, (ch + 1) & 1); CP_WAIT1(); }
        else              { CP_WAIT0(); }
        __syncthreads();

        const uint32_t ab = sb + p * ATILEB;
        const uint32_t bb = sb + 2 * ATILEB + p * BTILEB;
        #pragma unroll
        for (int k16 = 0; k16 < 4; k16++) {
            uint32_t a[4][4], b[2][4];
            #pragma unroll
            for (int mf = 0; mf < 4; mf++) {
                int row = wm + mf * 16 + (lane & 7) + ((lane >> 3) & 1) * 8;
                int c = k16 * 2 + (lane >> 4);
                LDSM4(a[mf], ab + row * 128 + ((c ^ (row & 7)) * 16));
            }
            #pragma unroll
            for (int nf2 = 0; nf2 < 2; nf2++) {
                int row = wn + nf2 * 16 + (lane & 7) + ((lane >> 4) & 1) * 8;
                int c = k16 * 2 + ((lane >> 3) & 1);
                LDSM4(b[nf2], bb + row * 128 + ((c ^ (row & 7)) * 16));
            }
            #pragma unroll
            for (int mf = 0; mf < 4; mf++)
                #pragma unroll
                for (int nf = 0; nf < 4; nf++)
                    MMA16816(acc[mf][nf], a[mf],
                             b[nf >> 1][(nf & 1) * 2], b[nf >> 1][(nf & 1) * 2 + 1]);
        }
        __syncthreads();
    }

    #pragma unroll
    for (int mf = 0; mf < 4; mf++) {
        #pragma unroll
        for (int nf = 0; nf < 4; nf++) {
            int r  = m0 + wm + mf * 16 + (lane >> 2);
            int cg = n0 + wn + nf * 8 + (lane & 3) * 2;
            float b0 = bias[cg], b1 = bias[cg + 1];
            float2 v0 = make_float2(acc[mf][nf][0] + b0, acc[mf][nf][1] + b1);
            float2 v1 = make_float2(acc[mf][nf][2] + b0, acc[mf][nf][3] + b1);
            *(float2*)(out + (size_t)r * Vv + cg) = v0;
            *(float2*)(out + (size_t)(r + 8) * Vv + cg) = v1;
        }
    }
}

// ---------------- fused log_softmax (512 threads; proven R12) ----------------
__global__ void lsm_kernel(float* __restrict__ out) {
    extern __shared__ float rowbuf[];
    __shared__ float warpred[16];
    __shared__ float s_bcast;
    const int tid = threadIdx.x;
    const int lane = tid & 31, wid = tid >> 5;
    float* p = out + (size_t)blockIdx.x * Vv;

    float mx = -1e30f;
    for (int i = tid; i < Vv / 4; i += 512) {
        float4 v = *(const float4*)(p + i * 4);
        *(float4*)(rowbuf + i * 4) = v;
        mx = fmaxf(mx, fmaxf(fmaxf(v.x, v.y), fmaxf(v.z, v.w)));
    }
    #pragma unroll
    for (int s = 16; s > 0; s >>= 1)
        mx = fmaxf(mx, __shfl_xor_sync(0xffffffffu, mx, s));
    if (lane == 0) warpred[wid] = mx;
    __syncthreads();
    mx = warpred[lane & 15];
    #pragma unroll
    for (int s = 8; s > 0; s >>= 1)
        mx = fmaxf(mx, __shfl_xor_sync(0xffffffffu, mx, s));
    mx = __shfl_sync(0xffffffffu, mx, 0);

    float sum = 0.f;
    for (int i = tid; i < Vv; i += 512) sum += fast_exp(rowbuf[i] - mx);
    #pragma unroll
    for (int s = 16; s > 0; s >>= 1)
        sum += __shfl_xor_sync(0xffffffffu, sum, s);
    __syncthreads();
    if (lane == 0) warpred[wid] = sum;
    __syncthreads();
    if (tid == 0) {
        float tot = 0.f;
        #pragma unroll
        for (int w = 0; w < 16; w++) tot += warpred[w];
        s_bcast = mx + logf(tot);
    }
    __syncthreads();
    float lse = s_bcast;

    for (int i = tid; i < Vv / 4; i += 512) {
        float4 v = *(const float4*)(rowbuf + i * 4);
        v.x -= lse; v.y -= lse; v.z -= lse; v.w -= lse;
        *(float4*)(p + i * 4) = v;
    }
}

// ---------------- host driver ------------------------------------------------
extern "C" void kernel_launch(void* const* d_in, const int* in_sizes, int n_in,
                              void* d_out, int out_size) {
    const float* enc_h  = (const float*)d_in[1];
    const int*   target = (const int*)  d_in[2];
    const float* emb    = (const float*)d_in[3];
    const float* w_ih   = (const float*)d_in[4];
    const float* w_hh   = (const float*)d_in[5];
    const float* b_ih   = (const float*)d_in[6];
    const float* b_hh   = (const float*)d_in[7];
    const float* w_out  = (const float*)d_in[8];
    const float* b_out  = (const float*)d_in[9];
    float* out = (float*)d_out;

    float *p_gi, *p_h0, *p_wih;
    __nv_bfloat16 *p_hsb, *p_wob;
    cudaGetSymbolAddress((void**)&p_gi,   g_gi);
    cudaGetSymbolAddress((void**)&p_h0,   g_h0);
    cudaGetSymbolAddress((void**)&p_wih,  g_wih_tf);
    cudaGetSymbolAddress((void**)&p_hsb,  g_hsb);
    cudaGetSymbolAddress((void**)&p_wob,  g_wob);

    float* hfinal = out + (size_t)MROWS * Vv;

    cudaFuncSetAttribute(logits_mma_kernel,
                         cudaFuncAttributeMaxDynamicSharedMemorySize, LSMEM);
    cudaFuncSetAttribute(gi_mma_kernel<0>,
                         cudaFuncAttributeMaxDynamicSharedMemorySize, GSMEM);
    cudaFuncSetAttribute(gi_mma_kernel<1>,
                         cudaFuncAttributeMaxDynamicSharedMemorySize, GSMEM);
    cudaFuncSetAttribute(gru_layer_kernel,
                         cudaFuncAttributeMaxDynamicSharedMemorySize, GRUSM);
    cudaFuncSetAttribute(lsm_kernel,
                         cudaFuncAttributeMaxDynamicSharedMemorySize, LSMSZ);

    // ---- prep --------------------------------------------------------------
    ids_kernel<<<(MROWS + 255) / 256, 256, 0, 0>>>(target);
    wihconv_kernel<<<2048, 256, 0, 0>>>(w_ih);

    // ---- layer 0 -----------------------------------------------------------
    gi_mma_kernel<1><<<dim3(H3 / 128, MROWS / 128), 256, GSMEM, 0>>>(
        nullptr, p_wih, b_ih, p_gi, emb);
    gru_layer_kernel<<<NBLK, 256, GRUSM, 0>>>(
        p_gi, w_hh, b_hh, enc_h, p_h0, nullptr, hfinal, Bb * Hh, Hh);

    // ---- w_out conversion (only needed before logits) ----------------------
    wconv_kernel<<<4096, 256, 0, 0>>>(w_out);

    // ---- layer 1 -----------------------------------------------------------
    gi_mma_kernel<0><<<dim3(H3 / 128, MROWS / 128), 256, GSMEM, 0>>>(
        p_h0, p_wih + (size_t)H3 * Hh, b_ih + H3, p_gi, nullptr);
    gru_layer_kernel<<<NBLK, 256, GRUSM, 0>>>(
        p_gi, w_hh + (size_t)H3 * Hh, b_hh + H3, enc_h + Bb * Hh,
        nullptr, p_hsb, hfinal + Bb * Hh, Hh, Tt * Hh);

    // ---- logits (bf16 HMMA, 128x128) ---------------------------------------
    logits_mma_kernel<<<dim3(Vv / NT, MROWS / MT), 256, LSMEM, 0>>>(
        p_hsb, p_wob, b_out, out);

    // ---- fused log_softmax -------------------------------------------------
    lsm_kernel<<<MROWS, 512, LSMSZ, 0>>>(out);
}

// round 16
// speedup vs baseline: 1.1414x; 1.0273x over previous
#include <cuda_runtime.h>
#include <cuda_bf16.h>
#include <math.h>
#include <stdint.h>

// Problem constants
#define Bb 32
#define Tt 128
#define Hh 1024
#define Ll 2
#define Vv 32000
#define H3 3072          // 3*H
#define MROWS (Tt*Bb)    // 4096
#define BOS 1
#define NBLK 128         // persistent recurrence blocks (all resident)

// Logits HMMA tiling (bf16): 128x128 block tile, 8 warps of 64x32 (R12 proven)
#define MT 128
#define NT 128
#define KC 64
#define NKC (Hh / KC)
#define ATILEB (MT * 128)      // 16 KB
#define BTILEB (NT * 128)      // 16 KB
#define LSMEM (2 * (ATILEB + BTILEB))   // 64 KB

// gi GEMM tiling (tf32)
#define GKC 32
#define GNKC (Hh / GKC)
#define GTILEB (128 * 128)
#define GSMEM (4 * GTILEB)              // 64 KB

// GRU smem: A(h) 32x1024 fp32 = 128KB, B(whh slice tf32) 24x1024 = 96KB
#define GRUSM (32 * 4096 + 24 * 4096)   // 229376 B

// fused log_softmax smem (one row)
#define LSMSZ (Vv * 4)

// ---------------- scratch (static device globals) ---------------------------
__device__ float g_gi[MROWS * H3];
__device__ float g_h0[MROWS * Hh];           // layer-0 outputs (tf32-rounded bits)
__device__ float g_wih_tf[Ll * H3 * Hh];     // w_ih pre-converted to tf32 bits
__device__ float g_hinit_tf[Ll * Bb * Hh];   // enc_h pre-rounded (staging only)
__device__ __nv_bfloat16 g_hsb[MROWS * Hh];
__device__ __nv_bfloat16 g_wob[(size_t)Vv * Hh];
__device__ float g_hbuf[2][Bb * Hh];         // ping-pong h (tf32-rounded bits)
__device__ int   g_ids[MROWS];
__device__ unsigned g_bar;

// ---------------- PTX helpers (all arch-portable: sm_80+) --------------------
__device__ __forceinline__ uint32_t smem_u32(const void* p) {
    uint32_t a;
    asm("{ .reg .u64 t; cvta.to.shared.u64 t, %1; cvt.u32.u64 %0, t; }"
        : "=r"(a) : "l"(p));
    return a;
}
__device__ __forceinline__ void cp_async16(uint32_t s, const void* g) {
    asm volatile("cp.async.cg.shared.global [%0], [%1], 16;"
                 :: "r"(s), "l"(g) : "memory");
}
#define CP_COMMIT() asm volatile("cp.async.commit_group;" ::: "memory")
#define CP_WAIT1()  asm volatile("cp.async.wait_group 1;" ::: "memory")
#define CP_WAIT0()  asm volatile("cp.async.wait_group 0;" ::: "memory")
#define LDSM4(r, addr) \
    asm volatile("ldmatrix.sync.aligned.m8n8.x4.shared.b16 {%0,%1,%2,%3}, [%4];" \
        : "=r"((r)[0]), "=r"((r)[1]), "=r"((r)[2]), "=r"((r)[3]) : "r"(addr))
#define MMA16816(c, a, b0, b1) \
    asm volatile("mma.sync.aligned.m16n8k16.row.col.f32.bf16.bf16.f32 " \
        "{%0,%1,%2,%3}, {%4,%5,%6,%7}, {%8,%9}, {%0,%1,%2,%3};" \
        : "+f"((c)[0]), "+f"((c)[1]), "+f"((c)[2]), "+f"((c)[3]) \
        : "r"((a)[0]), "r"((a)[1]), "r"((a)[2]), "r"((a)[3]), "r"(b0), "r"(b1))
#define MMA1688TF(c, a, b0, b1) \
    asm volatile("mma.sync.aligned.m16n8k8.row.col.f32.tf32.tf32.f32 " \
        "{%0,%1,%2,%3}, {%4,%5,%6,%7}, {%8,%9}, {%0,%1,%2,%3};" \
        : "+f"((c)[0]), "+f"((c)[1]), "+f"((c)[2]), "+f"((c)[3]) \
        : "r"((a)[0]), "r"((a)[1]), "r"((a)[2]), "r"((a)[3]), "r"(b0), "r"(b1))

__device__ __forceinline__ uint32_t lds_tf32(uint32_t addr) {
    float v; uint32_t o;
    asm("ld.shared.f32 %0, [%1];" : "=f"(v) : "r"(addr));
    asm("cvt.rna.tf32.f32 %0, %1;" : "=r"(o) : "f"(v));
    return o;
}
__device__ __forceinline__ uint32_t lds_u32(uint32_t addr) {
    uint32_t v;
    asm("ld.shared.b32 %0, [%1];" : "=r"(v) : "r"(addr));
    return v;
}
__device__ __forceinline__ uint32_t f2tf(float v) {
    uint32_t o;
    asm("cvt.rna.tf32.f32 %0, %1;" : "=r"(o) : "f"(v));
    return o;
}
// swizzle for 32-float (128B) rows
__device__ __forceinline__ uint32_t swz32(int r, int c) {
    return r * 128 + (((c >> 2) ^ (r & 7)) << 4) + ((c & 3) << 2);
}
// swizzle for 1024-float (4KB) rows
__device__ __forceinline__ uint32_t swzH(int r, int c) {
    return r * 4096 + ((((c >> 2) ^ (r & 7)) & 0xFFFF) << 4) + ((c & 3) << 2);
}

// FFMA-only e^x
__device__ __forceinline__ float fast_exp(float x) {
    float t = fmaxf(x * 1.4426950408889634f, -126.0f);
    float n = floorf(t);
    float f = t - n;
    float p = 0.0001540353f;
    p = p * f + 0.0013333558f;
    p = p * f + 0.0096181291f;
    p = p * f + 0.0555041087f;
    p = p * f + 0.2402265070f;
    p = p * f + 0.6931471806f;
    p = p * f + 1.0f;
    return __int_as_float(((int)n + 127) << 23) * p;
}

// ---------------- prep: ids + w_ih->tf32 + enc_h->tf32 -----------------------
__global__ void prep_kernel(const int* __restrict__ target,
                            const float* __restrict__ wih,
                            const float* __restrict__ ench) {
    int gid = blockIdx.x * blockDim.x + threadIdx.x;
    size_t stride = (size_t)gridDim.x * blockDim.x;
    if (gid < MROWS) {
        int t = gid / Bb, b = gid % Bb;
        g_ids[gid] = (t == 0) ? BOS : target[b * Tt + (t - 1)];
    }
    // enc_h rounded copy (staging source for GRU step 0)
    for (size_t i = gid; i < (size_t)Ll * Bb * Hh / 4; i += stride) {
        float4 v = ((const float4*)ench)[i];
        ((uint4*)g_hinit_tf)[i] = make_uint4(f2tf(v.x), f2tf(v.y), f2tf(v.z), f2tf(v.w));
    }
    // w_ih tf32 bits
    for (size_t i = gid; i < (size_t)Ll * H3 * Hh / 4; i += stride) {
        float4 v = ((const float4*)wih)[i];
        ((uint4*)g_wih_tf)[i] = make_uint4(f2tf(v.x), f2tf(v.y), f2tf(v.z), f2tf(v.w));
    }
}

// ---------------- persistent GRU layer: tf32 HMMA recurrence -----------------
// 128 blocks x 256 thr (1/SM, all resident). Block owns 8 h-cols = 24 whh
// rows staged once (tf32). hp carried in REGISTER across steps (thread
// (gb,gj) computes exactly its next-step hp) -> no per-step hp load, and the
// global h ping-pong stores tf32-rounded bits (consumed only by the MMA A
// path whose cvt is idempotent) -> A fragments are plain lds_u32, no CVTs.
__global__ void __launch_bounds__(256) gru_layer_kernel(
    const float* __restrict__ gi,      // [T][B][3H]
    const float* __restrict__ whh,     // [3H][H]
    const float* __restrict__ bhh,     // [3H]
    const float* __restrict__ hinit,   // [B][H] exact initial h (register seed)
    const float* __restrict__ hinittf, // [B][H] rounded initial h (staging)
    float* __restrict__ hist,          // fp32 history (tf32-rounded; or null)
    __nv_bfloat16* __restrict__ histb, // bf16 history (or null)
    float* __restrict__ hfin,          // final h destination [B][H] (exact)
    int tS, int bS)
{
    extern __shared__ float smf[];
    float* part = smf;                 // [8][792] aliased into A region
    const uint32_t aBase = smem_u32(smf);
    const uint32_t bBase = aBase + 32 * 4096;

    const int tid  = threadIdx.x;
    const int lane = tid & 31;
    const int w    = tid >> 5;
    const int j0   = blockIdx.x * 8;

    const int gb = tid >> 3;          // gate-math batch 0..31
    const int gj = tid & 7;           // gate-math col 0..7
    const int j  = j0 + gj;
    const float bhr = bhh[j];
    const float bhz = bhh[Hh + j];
    const float bhn = bhh[2 * Hh + j];

    // hp lives in a register across all steps
    float hp = hinit[(size_t)gb * Hh + j];

    // relative barrier base (g_bar is quiescent at kernel entry)
    const unsigned bar0 = *(volatile unsigned*)&g_bar;

    // ---- stage whh slice (24 rows) into smem, pre-converted to tf32 --------
    for (int idx = tid; idx < 24 * 256; idx += 256) {
        int n = idx >> 8, c = idx & 255;
        int grow = (n >> 3) * Hh + j0 + (n & 7);
        float4 v = *(const float4*)(whh + (size_t)grow * Hh + c * 4);
        uint4 o = make_uint4(f2tf(v.x), f2tf(v.y), f2tf(v.z), f2tf(v.w));
        *(uint4*)((char*)smf + (bBase - aBase) + n * 4096 + (((c ^ (n & 7)) & 0xFFFF) << 4)) = o;
    }
    __syncthreads();

    for (int t = 0; t < Tt; t++) {
        const float* __restrict__ hcur = (t == 0) ? hinittf : g_hbuf[t & 1];
        float* __restrict__ hnxt = g_hbuf[(t + 1) & 1];

        // ---- prefetch gi[t] (consumed post-MMA; latency hidden) ------------
        const float* git = gi + ((size_t)t * Bb + gb) * H3;
        float gir = git[j];
        float giz = git[Hh + j];
        float gin = git[2 * Hh + j];

        // ---- per-warp stage of own K-slice (cols w*128..w*128+127) ----------
        {
            const int c = w * 32 + lane;      // col-quad 0..255
            #pragma unroll 8
            for (int row = 0; row < 32; row++) {
                cp_async16(aBase + row * 4096 + (((c ^ (row & 7)) & 0xFF) << 4),
                           hcur + (size_t)row * Hh + c * 4);
            }
        }
        CP_COMMIT();

        const int k0w = w * 128;
        const int cL = lane & 3;

        // ---- B fragments for slab 0 (static smem; independent of staging) --
        uint32_t bf[3][2];
        #pragma unroll
        for (int nf = 0; nf < 3; nf++) {
            int rn = nf * 8 + (lane >> 2);
            bf[nf][0] = lds_u32(bBase + swzH(rn, k0w + cL));
            bf[nf][1] = lds_u32(bBase + swzH(rn, k0w + cL + 4));
        }

        CP_WAIT0();
        __syncwarp();

        // ---- tf32 MMA: warp w covers k in [w*128, w*128+128) ---------------
        float acc[2][3][4];
        #pragma unroll
        for (int m = 0; m < 2; m++)
            #pragma unroll
            for (int nf = 0; nf < 3; nf++)
                #pragma unroll
                for (int q = 0; q < 4; q++) acc[m][nf][q] = 0.f;

        #pragma unroll
        for (int k8 = 0; k8 < 16; k8++) {
            const int cA = k0w + k8 * 8 + cL;
            uint32_t a[2][4];
            #pragma unroll
            for (int m = 0; m < 2; m++) {
                int r = m * 16 + (lane >> 2);
                a[m][0] = lds_u32(aBase + swzH(r, cA));
                a[m][1] = lds_u32(aBase + swzH(r + 8, cA));
                a[m][2] = lds_u32(aBase + swzH(r, cA + 4));
                a[m][3] = lds_u32(aBase + swzH(r + 8, cA + 4));
            }
            uint32_t bn[3][2];
            if (k8 < 15) {
                const int cB = k0w + (k8 + 1) * 8 + cL;
                #pragma unroll
                for (int nf = 0; nf < 3; nf++) {
                    int rn = nf * 8 + (lane >> 2);
                    bn[nf][0] = lds_u32(bBase + swzH(rn, cB));
                    bn[nf][1] = lds_u32(bBase + swzH(rn, cB + 4));
                }
            }
            #pragma unroll
            for (int m = 0; m < 2; m++)
                #pragma unroll
                for (int nf = 0; nf < 3; nf++)
                    MMA1688TF(acc[m][nf], a[m], bf[nf][0], bf[nf][1]);
            if (k8 < 15) {
                #pragma unroll
                for (int nf = 0; nf < 3; nf++) {
                    bf[nf][0] = bn[nf][0];
                    bf[nf][1] = bn[nf][1];
                }
            }
        }
        __syncthreads();   // all MMA reads of A done before aliased writes

        // ---- write partials: part[w][rid*33 + batch] ------------------------
        #pragma unroll
        for (int m = 0; m < 2; m++) {
            #pragma unroll
            for (int nf = 0; nf < 3; nf++) {
                int rowm = m * 16 + (lane >> 2);
                int col = nf * 8 + 2 * (lane & 3);
                float* pw = part + w * 792;
                pw[col * 33 + rowm]           = acc[m][nf][0];
                pw[(col + 1) * 33 + rowm]     = acc[m][nf][1];
                pw[col * 33 + rowm + 8]       = acc[m][nf][2];
                pw[(col + 1) * 33 + rowm + 8] = acc[m][nf][3];
            }
        }
        __syncthreads();

        // ---- fused 8-way reduce + gate math: thread owns (gb, gj) -----------
        {
            float ghr = bhr, ghz = bhz, ghn = bhn;
            #pragma unroll
            for (int ww = 0; ww < 8; ww++) {
                const float* pw = part + ww * 792;
                ghr += pw[gj * 33 + gb];
                ghz += pw[(8 + gj) * 33 + gb];
                ghn += pw[(16 + gj) * 33 + gb];
            }
            float r_ = 1.f / (1.f + expf(-(gir + ghr)));
            float z_ = 1.f / (1.f + expf(-(giz + ghz)));
            float n_ = tanhf(gin + r_ * ghn);
            float hn = (1.f - z_) * n_ + z_ * hp;
            size_t oidx = (size_t)t * tS + (size_t)gb * bS + j;
            float hnr = __uint_as_float(f2tf(hn));   // tf32 pre-round
            if (histb) histb[oidx] = __float2bfloat16(hn);
            else       hist[oidx] = hnr;
            hnxt[(size_t)gb * Hh + j] = hnr;
            if (t == Tt - 1) hfin[(size_t)gb * Hh + j] = hn;
            hp = hn;                                  // register carry
        }

        // ---- grid barrier (release/acquire, CG pattern) ---------------------
        __syncthreads();
        if (tid == 0) {
            asm volatile("red.release.gpu.add.u32 [%0], %1;"
                         :: "l"(&g_bar), "r"(1u) : "memory");
            unsigned tgt = (unsigned)(NBLK * (t + 1));
            unsigned v;
            do {
                asm volatile("ld.acquire.gpu.u32 %0, [%1];"
                             : "=r"(v) : "l"(&g_bar) : "memory");
                if ((v - bar0) >= tgt) break;
                __nanosleep(32);
            } while (true);
        }
        __syncthreads();
    }
}

// ---------------- tf32 gi GEMM: pre-tf32 operands; optional wconv tail -------
#define GPREF(ch, p) do {                                                       \
    int _k0 = (ch) * GKC;                                                       \
    uint32_t _ab = sb + (p) * GTILEB;                                           \
    uint32_t _bb = sb + 2 * GTILEB + (p) * GTILEB;                              \
    _Pragma("unroll")                                                           \
    for (int _it = 0; _it < 4; _it++) {                                         \
        int _idx = _it * 256 + tid, _row = _idx >> 3, _c = _idx & 7;            \
        const float* _as = GATHER                                               \
            ? emb + (size_t)g_ids[m0 + _row] * Hh + _k0 + _c * 4                \
            : A + (size_t)(m0 + _row) * Hh + _k0 + _c * 4;                      \
        cp_async16(_ab + _row * 128 + ((_c ^ (_row & 7)) * 16), _as);           \
        cp_async16(_bb + _row * 128 + ((_c ^ (_row & 7)) * 16),                 \
                   W + (size_t)(n0 + _row) * Hh + _k0 + _c * 4);                \
    }                                                                           \
    CP_COMMIT();                                                                \
} while (0)

template<int GATHER, int WCONV>
__global__ void __launch_bounds__(256) gi_mma_kernel(
    const float* __restrict__ A, const float* __restrict__ W,
    const float* __restrict__ bias, float* __restrict__ C,
    const float* __restrict__ emb, const float* __restrict__ wout)
{
    extern __shared__ char smem[];
    const int tid  = threadIdx.x;
    const int lane = tid & 31;
    const int warp = tid >> 5;
    const int m0 = blockIdx.y * 128;
    const int n0 = blockIdx.x * 128;
    const int wm = (warp & 1) * 64;
    const int wn = (warp >> 1) * 32;
    uint32_t sb = smem_u32(smem);

    float acc[4][4][4];
    #pragma unroll
    for (int i = 0; i < 4; i++)
        #pragma unroll
        for (int jj = 0; jj < 4; jj++)
            #pragma unroll
            for (int k = 0; k < 4; k++) acc[i][jj][k] = 0.f;

    GPREF(0, 0);
    for (int ch = 0; ch < GNKC; ch++) {
        const int p = ch & 1;
        if (ch + 1 < GNKC) { GPREF(ch + 1, (ch + 1) & 1); CP_WAIT1(); }
        else               { CP_WAIT0(); }
        __syncthreads();

        const uint32_t ab = sb + p * GTILEB;
        const uint32_t bb = sb + 2 * GTILEB + p * GTILEB;
        #pragma unroll
        for (int k8 = 0; k8 < 4; k8++) {
            uint32_t a[4][4], b[4][2];
            #pragma unroll
            for (int mf = 0; mf < 4; mf++) {
                int r = wm + mf * 16 + (lane >> 2);
                int c = k8 * 8 + (lane & 3);
                if (GATHER) {
                    a[mf][0] = lds_tf32(ab + swz32(r, c));
                    a[mf][1] = lds_tf32(ab + swz32(r + 8, c));
                    a[mf][2] = lds_tf32(ab + swz32(r, c + 4));
                    a[mf][3] = lds_tf32(ab + swz32(r + 8, c + 4));
                } else {
                    a[mf][0] = lds_u32(ab + swz32(r, c));
                    a[mf][1] = lds_u32(ab + swz32(r + 8, c));
                    a[mf][2] = lds_u32(ab + swz32(r, c + 4));
                    a[mf][3] = lds_u32(ab + swz32(r + 8, c + 4));
                }
            }
            #pragma unroll
            for (int nf = 0; nf < 4; nf++) {
                int rn = wn + nf * 8 + (lane >> 2);
                int ck = k8 * 8 + (lane & 3);
                b[nf][0] = lds_u32(bb + swz32(rn, ck));
                b[nf][1] = lds_u32(bb + swz32(rn, ck + 4));
            }
            #pragma unroll
            for (int mf = 0; mf < 4; mf++)
                #pragma unroll
                for (int nf = 0; nf < 4; nf++)
                    MMA1688TF(acc[mf][nf], a[mf], b[nf][0], b[nf][1]);
        }
        __syncthreads();
    }

    #pragma unroll
    for (int mf = 0; mf < 4; mf++) {
        #pragma unroll
        for (int nf = 0; nf < 4; nf++) {
            int r  = m0 + wm + mf * 16 + (lane >> 2);
            int cg = n0 + wn + nf * 8 + (lane & 3) * 2;
            float b0 = bias[cg], b1 = bias[cg + 1];
            float2 v0 = make_float2(acc[mf][nf][0] + b0, acc[mf][nf][1] + b1);
            float2 v1 = make_float2(acc[mf][nf][2] + b0, acc[mf][nf][3] + b1);
            *(float2*)(C + (size_t)r * H3 + cg) = v0;
            *(float2*)(C + (size_t)(r + 8) * H3 + cg) = v1;
        }
    }

    // ---- folded w_out -> bf16 conversion (overlaps other blocks' MMA) ------
    if (WCONV) {
        size_t n = (size_t)Vv * Hh / 4;
        size_t gstride = (size_t)gridDim.x * gridDim.y * 256;
        size_t base = ((size_t)blockIdx.y * gridDim.x + blockIdx.x) * 256 + tid;
        for (size_t i = base; i < n; i += gstride) {
            float4 v = ((const float4*)wout)[i];
            __nv_bfloat162 lo = __floats2bfloat162_rn(v.x, v.y);
            __nv_bfloat162 hi = __floats2bfloat162_rn(v.z, v.w);
            ((uint2*)g_wob)[i] = make_uint2(*(uint32_t*)&lo, *(uint32_t*)&hi);
        }
    }
}

// ---------------- bf16 HMMA logits GEMM: 128x128 tile (R12 proven) -----------
#define PREF(ch, p) do {                                                        \
    int _k0 = (ch) * KC;                                                        \
    uint32_t _ab = sb + (p) * ATILEB;                                           \
    uint32_t _bb = sb + 2 * ATILEB + (p) * BTILEB;                              \
    _Pragma("unroll")                                                           \
    for (int _it = 0; _it < 4; _it++) {                                         \
        int _idx = _it * 256 + tid, _row = _idx >> 3, _c = _idx & 7;            \
        cp_async16(_ab + _row * 128 + ((_c ^ (_row & 7)) * 16),                 \
                   hsb + (size_t)(m0 + _row) * Hh + _k0 + _c * 8);              \
        cp_async16(_bb + _row * 128 + ((_c ^ (_row & 7)) * 16),                 \
                   wob + (size_t)(n0 + _row) * Hh + _k0 + _c * 8);              \
    }                                                                           \
    CP_COMMIT();                                                                \
} while (0)

__global__ void __launch_bounds__(256) logits_mma_kernel(
    const __nv_bfloat16* __restrict__ hsb,
    const __nv_bfloat16* __restrict__ wob,
    const float* __restrict__ bias,
    float* __restrict__ out)
{
    extern __shared__ char smem[];
    const int tid  = threadIdx.x;
    const int lane = tid & 31;
    const int warp = tid >> 5;
    const int m0 = blockIdx.y * MT;
    const int n0 = blockIdx.x * NT;
    const int wm = (warp & 1) * 64;
    const int wn = (warp >> 1) * 32;
    uint32_t sb = smem_u32(smem);

    float acc[4][4][4];
    #pragma unroll
    for (int i = 0; i < 4; i++)
        #pragma unroll
        for (int jj = 0; jj < 4; jj++)
            #pragma unroll
            for (int k = 0; k < 4; k++) acc[i][jj][k] = 0.f;

    PREF(0, 0);
    for (int ch = 0; ch < NKC; ch++) {
        const int p = ch & 1;
        if (ch + 1 < NKC) { PREF(ch + 1, (ch + 1) & 1); CP_WAIT1(); }
        else              { CP_WAIT0(); }
        __syncthreads();

        const uint32_t ab = sb + p * ATILEB;
        const uint32_t bb = sb + 2 * ATILEB + p * BTILEB;
        #pragma unroll
        for (int k16 = 0; k16 < 4; k16++) {
            uint32_t a[4][4], b[2][4];
            #pragma unroll
            for (int mf = 0; mf < 4; mf++) {
                int row = wm + mf * 16 + (lane & 7) + ((lane >> 3) & 1) * 8;
                int c = k16 * 2 + (lane >> 4);
                LDSM4(a[mf], ab + row * 128 + ((c ^ (row & 7)) * 16));
            }
            #pragma unroll
            for (int nf2 = 0; nf2 < 2; nf2++) {
                int row = wn + nf2 * 16 + (lane & 7) + ((lane >> 4) & 1) * 8;
                int c = k16 * 2 + ((lane >> 3) & 1);
                LDSM4(b[nf2], bb + row * 128 + ((c ^ (row & 7)) * 16));
            }
            #pragma unroll
            for (int mf = 0; mf < 4; mf++)
                #pragma unroll
                for (int nf = 0; nf < 4; nf++)
                    MMA16816(acc[mf][nf], a[mf],
                             b[nf >> 1][(nf & 1) * 2], b[nf >> 1][(nf & 1) * 2 + 1]);
        }
        __syncthreads();
    }

    #pragma unroll
    for (int mf = 0; mf < 4; mf++) {
        #pragma unroll
        for (int nf = 0; nf < 4; nf++) {
            int r  = m0 + wm + mf * 16 + (lane >> 2);
            int cg = n0 + wn + nf * 8 + (lane & 3) * 2;
            float b0 = bias[cg], b1 = bias[cg + 1];
            float2 v0 = make_float2(acc[mf][nf][0] + b0, acc[mf][nf][1] + b1);
            float2 v1 = make_float2(acc[mf][nf][2] + b0, acc[mf][nf][3] + b1);
            *(float2*)(out + (size_t)r * Vv + cg) = v0;
            *(float2*)(out + (size_t)(r + 8) * Vv + cg) = v1;
        }
    }
}

// ---------------- fused log_softmax (512 threads; proven R12) ----------------
__global__ void lsm_kernel(float* __restrict__ out) {
    extern __shared__ float rowbuf[];
    __shared__ float warpred[16];
    __shared__ float s_bcast;
    const int tid = threadIdx.x;
    const int lane = tid & 31, wid = tid >> 5;
    float* p = out + (size_t)blockIdx.x * Vv;

    float mx = -1e30f;
    for (int i = tid; i < Vv / 4; i += 512) {
        float4 v = *(const float4*)(p + i * 4);
        *(float4*)(rowbuf + i * 4) = v;
        mx = fmaxf(mx, fmaxf(fmaxf(v.x, v.y), fmaxf(v.z, v.w)));
    }
    #pragma unroll
    for (int s = 16; s > 0; s >>= 1)
        mx = fmaxf(mx, __shfl_xor_sync(0xffffffffu, mx, s));
    if (lane == 0) warpred[wid] = mx;
    __syncthreads();
    mx = warpred[lane & 15];
    #pragma unroll
    for (int s = 8; s > 0; s >>= 1)
        mx = fmaxf(mx, __shfl_xor_sync(0xffffffffu, mx, s));
    mx = __shfl_sync(0xffffffffu, mx, 0);

    float sum = 0.f;
    for (int i = tid; i < Vv; i += 512) sum += fast_exp(rowbuf[i] - mx);
    #pragma unroll
    for (int s = 16; s > 0; s >>= 1)
        sum += __shfl_xor_sync(0xffffffffu, sum, s);
    __syncthreads();
    if (lane == 0) warpred[wid] = sum;
    __syncthreads();
    if (tid == 0) {
        float tot = 0.f;
        #pragma unroll
        for (int w = 0; w < 16; w++) tot += warpred[w];
        s_bcast = mx + logf(tot);
    }
    __syncthreads();
    float lse = s_bcast;

    for (int i = tid; i < Vv / 4; i += 512) {
        float4 v = *(const float4*)(rowbuf + i * 4);
        v.x -= lse; v.y -= lse; v.z -= lse; v.w -= lse;
        *(float4*)(p + i * 4) = v;
    }
}

// ---------------- host driver ------------------------------------------------
extern "C" void kernel_launch(void* const* d_in, const int* in_sizes, int n_in,
                              void* d_out, int out_size) {
    const float* enc_h  = (const float*)d_in[1];
    const int*   target = (const int*)  d_in[2];
    const float* emb    = (const float*)d_in[3];
    const float* w_ih   = (const float*)d_in[4];
    const float* w_hh   = (const float*)d_in[5];
    const float* b_ih   = (const float*)d_in[6];
    const float* b_hh   = (const float*)d_in[7];
    const float* w_out  = (const float*)d_in[8];
    const float* b_out  = (const float*)d_in[9];
    float* out = (float*)d_out;

    float *p_gi, *p_h0, *p_wih, *p_hinit;
    __nv_bfloat16 *p_hsb, *p_wob;
    cudaGetSymbolAddress((void**)&p_gi,    g_gi);
    cudaGetSymbolAddress((void**)&p_h0,    g_h0);
    cudaGetSymbolAddress((void**)&p_wih,   g_wih_tf);
    cudaGetSymbolAddress((void**)&p_hinit, g_hinit_tf);
    cudaGetSymbolAddress((void**)&p_hsb,   g_hsb);
    cudaGetSymbolAddress((void**)&p_wob,   g_wob);

    float* hfinal = out + (size_t)MROWS * Vv;

    cudaFuncSetAttribute(logits_mma_kernel,
                         cudaFuncAttributeMaxDynamicSharedMemorySize, LSMEM);
    cudaFuncSetAttribute((gi_mma_kernel<0,0>),
                         cudaFuncAttributeMaxDynamicSharedMemorySize, GSMEM);
    cudaFuncSetAttribute((gi_mma_kernel<1,1>),
                         cudaFuncAttributeMaxDynamicSharedMemorySize, GSMEM);
    cudaFuncSetAttribute(gru_layer_kernel,
                         cudaFuncAttributeMaxDynamicSharedMemorySize, GRUSM);
    cudaFuncSetAttribute(lsm_kernel,
                         cudaFuncAttributeMaxDynamicSharedMemorySize, LSMSZ);

    // ---- prep (ids + w_ih tf32 + enc_h tf32) -------------------------------
    prep_kernel<<<2048, 256, 0, 0>>>(target, w_ih, enc_h);

    // ---- layer 0 (gi0 with folded w_out conversion tail) -------------------
    gi_mma_kernel<1,1><<<dim3(H3 / 128, MROWS / 128), 256, GSMEM, 0>>>(
        nullptr, p_wih, b_ih, p_gi, emb, w_out);
    gru_layer_kernel<<<NBLK, 256, GRUSM, 0>>>(
        p_gi, w_hh, b_hh, enc_h, p_hinit, p_h0, nullptr, hfinal, Bb * Hh, Hh);

    // ---- layer 1 -----------------------------------------------------------
    gi_mma_kernel<0,0><<<dim3(H3 / 128, MROWS / 128), 256, GSMEM, 0>>>(
        p_h0, p_wih + (size_t)H3 * Hh, b_ih + H3, p_gi, nullptr, nullptr);
    gru_layer_kernel<<<NBLK, 256, GRUSM, 0>>>(
        p_gi, w_hh + (size_t)H3 * Hh, b_hh + H3, enc_h + Bb * Hh,
        p_hinit + Bb * Hh, nullptr, p_hsb, hfinal + Bb * Hh, Hh, Tt * Hh);

    // ---- logits (bf16 HMMA, 128x128) ---------------------------------------
    logits_mma_kernel<<<dim3(Vv / NT, MROWS / MT), 256, LSMEM, 0>>>(
        p_hsb, p_wob, b_out, out);

    // ---- fused log_softmax -------------------------------------------------
    lsm_kernel<<<MROWS, 512, LSMSZ, 0>>>(out);
}